// round 12
// baseline (speedup 1.0000x reference)
#include <cuda_runtime.h>
#include <cuda_bf16.h>
#include <stdint.h>
#include <math.h>

// ---------------- problem constants ----------------
#define DIMC   256
#define HEADS  8
#define HD     32
#define WSZ    16
#define WN     16
#define KS     3
#define BATCH  16
#define IMG    64
#define TOK    144
#define MROWS  36864               // DIMC*TOK

// ---------------- scratch ----------------
__device__ float          g_qkv[MROWS * 3 * DIMC];
__device__ float          g_kp [MROWS * DIMC];
__device__ float          g_s  [WN * DIMC * DIMC];
__device__ float          g_y  [WN * BATCH * 256 * DIMC];   // (w,b,pos,cout)
__device__ __nv_bfloat16  g_aph[MROWS * DIMC];              // A hi plane (kt, then attn-o)
__device__ __nv_bfloat16  g_apl[MROWS * DIMC];              // A lo plane
__device__ __nv_bfloat16  g_bqh[3 * DIMC * DIMC];           // wqkv^T hi [n][k]
__device__ __nv_bfloat16  g_bql[3 * DIMC * DIMC];
__device__ __nv_bfloat16  g_bwh[DIMC * DIMC];               // wout^T hi [n][k]
__device__ __nv_bfloat16  g_bwl[DIMC * DIMC];
__device__ __nv_bfloat16  g_wbh[WN * DIMC * 9 * DIMC];      // gated conv W hi [w][cout][tap][cin]
__device__ __nv_bfloat16  g_wbl[WN * DIMC * 9 * DIMC];
__device__ __nv_bfloat16  g_xth[BATCH * WN * 4 * 324 * 64]; // x windows hi [(b*16+w)*4+chunk][row][cin64]
__device__ __nv_bfloat16  g_xtl[BATCH * WN * 4 * 324 * 64];

// ============================================================================
// helpers
// ============================================================================
__device__ __forceinline__ uint32_t smem_u32(const void* p) {
    uint32_t a;
    asm("{ .reg .u64 t; cvta.to.shared.u64 t, %1; cvt.u32.u64 %0, t; }" : "=r"(a) : "l"(p));
    return a;
}
__device__ __forceinline__ void split2(float v, __nv_bfloat16& h, __nv_bfloat16& l) {
    h = __float2bfloat16(v);
    l = __float2bfloat16(v - __bfloat162float(h));
}
__device__ __forceinline__ void mma16816(float* d, const uint32_t* a, const uint32_t* b) {
    asm volatile("mma.sync.aligned.m16n8k16.row.col.f32.bf16.bf16.f32 "
        "{%0,%1,%2,%3}, {%4,%5,%6,%7}, {%8,%9}, {%0,%1,%2,%3};"
        : "+f"(d[0]), "+f"(d[1]), "+f"(d[2]), "+f"(d[3])
        : "r"(a[0]), "r"(a[1]), "r"(a[2]), "r"(a[3]), "r"(b[0]), "r"(b[1]));
}
__device__ __forceinline__ void ldsm4(uint32_t* r, uint32_t addr) {
    asm volatile("ldmatrix.sync.aligned.m8n8.x4.shared.b16 {%0,%1,%2,%3}, [%4];"
        : "=r"(r[0]), "=r"(r[1]), "=r"(r[2]), "=r"(r[3]) : "r"(addr));
}
__device__ __forceinline__ void cp16(uint32_t dst, const void* src) {
    asm volatile("cp.async.cg.shared.global [%0], [%1], 16;" :: "r"(dst), "l"(src));
}
#define CP_COMMIT() asm volatile("cp.async.commit_group;" ::: "memory")
#define CP_WAIT0()  asm volatile("cp.async.wait_group 0;" ::: "memory")
#define CP_WAIT1()  asm volatile("cp.async.wait_group 1;" ::: "memory")

// packed f32x2 (Blackwell): one instr = two independent fp32 FMAs
typedef unsigned long long u64p;
__device__ __forceinline__ u64p pk2(float lo, float hi) {
    u64p r; asm("mov.b64 %0, {%1, %2};" : "=l"(r) : "f"(lo), "f"(hi)); return r;
}
__device__ __forceinline__ void up2(u64p v, float& lo, float& hi) {
    asm("mov.b64 {%0, %1}, %2;" : "=f"(lo), "=f"(hi) : "l"(v));
}
__device__ __forceinline__ void ffma2(u64p& d, u64p a, u64p b) {
    asm("fma.rn.f32x2 %0, %1, %2, %0;" : "+l"(d) : "l"(a), "l"(b));
}

// Fill a 128x64-bf16 tile (XOR-swizzled 128B rows) via cp.async. NT threads.
__device__ __forceinline__ void fill_tile256(uint32_t dst, const __nv_bfloat16* src,
                                             int rstride, int tid) {
#pragma unroll
    for (int i = 0; i < 4; i++) {
        int idx = tid + i * 256;
        int r = idx >> 3, q = idx & 7;
        cp16(dst + r * 128 + ((q ^ (r & 7)) << 4), src + (size_t)r * rstride + q * 8);
    }
}
__device__ __forceinline__ void fill_tile512(uint32_t dst, const __nv_bfloat16* src,
                                             int rstride, int tid) {
#pragma unroll
    for (int i = 0; i < 2; i++) {
        int idx = tid + i * 512;
        int r = idx >> 3, q = idx & 7;
        cp16(dst + r * 128 + ((q ^ (r & 7)) << 4), src + (size_t)r * rstride + q * 8);
    }
}

// ============================================================================
// pack kernels
// ============================================================================
__global__ void build_kt_tr(const float* __restrict__ conv_w) {
    __shared__ float sm[64][145];
    const int tid = threadIdx.x;
    const int c1 = blockIdx.x;
    const int cc0 = blockIdx.y * 64;
    const int w = c1 & 15, b = c1 >> 4;
    const float* src = conv_w + ((size_t)(w * 16 + b) * 256 + cc0) * 144;
    for (int idx = tid; idx < 64 * 144; idx += 256) {
        int c = idx / 144, l = idx - c * 144;
        sm[c][l] = src[c * 144 + l];
    }
    __syncthreads();
    for (int idx = tid; idx < 144 * 64; idx += 256) {
        int l = idx >> 6, c = idx & 63;
        __nv_bfloat16 h, lo;
        split2(sm[c][l], h, lo);
        size_t o = (size_t)(c1 * 144 + l) * 256 + cc0 + c;
        g_aph[o] = h;
        g_apl[o] = lo;
    }
}
__global__ void pack_bt(const float* __restrict__ W, __nv_bfloat16* __restrict__ oh,
                        __nv_bfloat16* __restrict__ ol, int N) {
    int idx = blockIdx.x * 256 + threadIdx.x;
    int k = idx & 255;
    int n = idx >> 8;
    __nv_bfloat16 h, l;
    split2(W[(size_t)k * N + n], h, l);
    oh[idx] = h;
    ol[idx] = l;
}
__global__ void pack_x(const float* __restrict__ x) {
    extern __shared__ float sm[];        // [64][325]
    const int tid = threadIdx.x;
    const int wb = blockIdx.x;           // b*16 + w
    const int b = wb >> 4, w = wb & 15;
    const int h0 = (w >> 2) * WSZ;
    const int w0 = (w & 3) * WSZ;
    for (int chunk = 0; chunk < 4; chunk++) {
        const int c0 = chunk * 64;
        __syncthreads();
        for (int i = tid; i < 64 * 324; i += 256) {
            int ci = i / 324;
            int rem = i - ci * 324;
            int yy = rem / 18;
            int xx = rem - yy * 18;
            float v = 0.f;
            if ((unsigned)(yy - 1) < 16u && (unsigned)(xx - 1) < 16u)
                v = x[((size_t)(b * DIMC + c0 + ci) * IMG + h0 + yy - 1) * IMG + w0 + xx - 1];
            sm[ci * 325 + rem] = v;
        }
        __syncthreads();
        size_t obase = ((size_t)(wb * 4 + chunk)) * 324 * 64;
        for (int i = tid; i < 324 * 64; i += 256) {
            int row = i >> 6, ci = i & 63;
            __nv_bfloat16 h, l;
            split2(sm[ci * 325 + row], h, l);
            g_xth[obase + i] = h;
            g_xtl[obase + i] = l;
        }
    }
}

// ============================================================================
// GEMM: C[M,N] = A @ B^T + bias, K=256 (unchanged from R11 best).
// ============================================================================
#define G_AH 0
#define G_AL 16384
#define G_BH 32768
#define G_BL 49152
#define G_SMEM 65536

__global__ void __launch_bounds__(256, 2)
gemm_mma(const __nv_bfloat16* __restrict__ Ah, const __nv_bfloat16* __restrict__ Al,
         const __nv_bfloat16* __restrict__ Bh, const __nv_bfloat16* __restrict__ Bl,
         const float* __restrict__ bias, float* __restrict__ C, int N) {
    extern __shared__ char smem[];
    const uint32_t sb = smem_u32(smem);
    const int tid = threadIdx.x;
    const int lane = tid & 31;
    const int wid = tid >> 5;
    const int wm = wid & 3, wn = wid >> 2;
    const int m0 = blockIdx.y * 128, n0 = blockIdx.x * 128;
    const int lm = lane & 15, kh = lane >> 4;
    const int quad = lane >> 2, qt = lane & 3;
    const int l7 = lane & 7;
    const int kbit = (lane >> 3) & 1;
    const int nloc = ((lane >> 4) << 3) | l7;

    float acc[2][8][4] = {};

#pragma unroll 1
    for (int kc = 0; kc < 4; kc++) {
        const int k0 = kc * 64;
        fill_tile256(sb + G_AH, Ah + (size_t)m0 * 256 + k0, 256, tid);
        fill_tile256(sb + G_AL, Al + (size_t)m0 * 256 + k0, 256, tid);
        fill_tile256(sb + G_BH, Bh + (size_t)n0 * 256 + k0, 256, tid);
        fill_tile256(sb + G_BL, Bl + (size_t)n0 * 256 + k0, 256, tid);
        CP_COMMIT();
        CP_WAIT0();
        __syncthreads();

        const uint32_t AbH = sb + G_AH;
        const uint32_t AbL = sb + G_AL;
        const uint32_t BbH = sb + G_BH + (wn * 64 + nloc) * 128;
        const uint32_t BbL = sb + G_BL + (wn * 64 + nloc) * 128;
#pragma unroll
        for (int ks = 0; ks < 4; ks++) {
            uint32_t ah[2][4], al[2][4];
#pragma unroll
            for (int fm = 0; fm < 2; fm++) {
                int m = wm * 32 + fm * 16 + lm;
                uint32_t acol = (uint32_t)(((ks * 2 + kh) ^ (lm & 7)) << 4);
                ldsm4(ah[fm], AbH + m * 128 + acol);
                ldsm4(al[fm], AbL + m * 128 + acol);
            }
            const uint32_t bcol = (uint32_t)(((ks * 2 + kbit) ^ l7) << 4);
            uint32_t bh[4][4], bl[4][4];
#pragma unroll
            for (int p = 0; p < 4; p++) {
                ldsm4(bh[p], BbH + p * 2048 + bcol);
                ldsm4(bl[p], BbL + p * 2048 + bcol);
            }
#pragma unroll
            for (int p = 0; p < 4; p++)
#pragma unroll
                for (int fm = 0; fm < 2; fm++) {
                    mma16816(acc[fm][2 * p],     ah[fm], bh[p]);
                    mma16816(acc[fm][2 * p + 1], ah[fm], bh[p] + 2);
                }
#pragma unroll
            for (int p = 0; p < 4; p++)
#pragma unroll
                for (int fm = 0; fm < 2; fm++) {
                    mma16816(acc[fm][2 * p],     ah[fm], bl[p]);
                    mma16816(acc[fm][2 * p + 1], ah[fm], bl[p] + 2);
                }
#pragma unroll
            for (int p = 0; p < 4; p++)
#pragma unroll
                for (int fm = 0; fm < 2; fm++) {
                    mma16816(acc[fm][2 * p],     al[fm], bh[p]);
                    mma16816(acc[fm][2 * p + 1], al[fm], bh[p] + 2);
                }
        }
        __syncthreads();
    }

#pragma unroll
    for (int fm = 0; fm < 2; fm++) {
        int m = m0 + wm * 32 + fm * 16 + quad;
#pragma unroll
        for (int fn = 0; fn < 8; fn++) {
            int col = n0 + wn * 64 + fn * 8 + qt * 2;
            float b0 = bias[col], b1 = bias[col + 1];
            float* c = acc[fm][fn];
            *(float2*)&C[(size_t)m * N + col]       = make_float2(c[0] + b0, c[1] + b1);
            *(float2*)&C[(size_t)(m + 8) * N + col] = make_float2(c[2] + b0, c[3] + b1);
        }
    }
}

// ============================================================================
// attention — single pass, packed f32x2 FMA (unchanged from R11)
// ============================================================================
__global__ void attn_kernel(const float* __restrict__ qkv) {
    const int c1 = blockIdx.x;
    const int h  = blockIdx.y;
    __shared__ float ks[TOK][HD];
    __shared__ float vs[TOK][HD];

    for (int idx = threadIdx.x; idx < TOK * HD; idx += blockDim.x) {
        int t = idx >> 5, e = idx & 31;
        size_t base = (size_t)(c1 * TOK + t) * 768 + h * HD + e;
        ks[t][e] = qkv[base + 256];
        vs[t][e] = qkv[base + 512];
    }
    __syncthreads();

    const int t = threadIdx.x;
    if (t < TOK) {
        const float scale = 0.17677669529663687f;
        u64p q2[16];
        {
            const float2* qsrc = (const float2*)(qkv + (size_t)(c1 * TOK + t) * 768 + h * HD);
#pragma unroll
            for (int i = 0; i < 16; i++) {
                float2 v = qsrc[i];
                q2[i] = pk2(v.x * scale, v.y * scale);
            }
        }

        u64p a2[16];
#pragma unroll
        for (int i = 0; i < 16; i++) a2[i] = pk2(0.f, 0.f);
        float denom = 0.f;

        for (int j = 0; j < TOK; j++) {
            const u64p* k2 = (const u64p*)ks[j];
            u64p s0 = pk2(0.f, 0.f), s1 = s0, s2 = s0, s3 = s0;
#pragma unroll
            for (int i = 0; i < 16; i += 4) {
                ffma2(s0, q2[i],     k2[i]);
                ffma2(s1, q2[i + 1], k2[i + 1]);
                ffma2(s2, q2[i + 2], k2[i + 2]);
                ffma2(s3, q2[i + 3], k2[i + 3]);
            }
            float x0, x1, y0, y1, z0, z1, w0, w1;
            up2(s0, x0, x1); up2(s1, y0, y1); up2(s2, z0, z1); up2(s3, w0, w1);
            float sc = ((x0 + x1) + (y0 + y1)) + ((z0 + z1) + (w0 + w1));
            float pexp = __expf(sc);
            denom += pexp;
            u64p pe2 = pk2(pexp, pexp);
            const u64p* v2 = (const u64p*)vs[j];
#pragma unroll
            for (int i = 0; i < 16; i++) ffma2(a2[i], pe2, v2[i]);
        }
        float inv = 1.f / denom;
        size_t ob = (size_t)(c1 * TOK + t) * DIMC + h * HD;
#pragma unroll
        for (int i = 0; i < 16; i++) {
            float v0, v1;
            up2(a2[i], v0, v1);
            __nv_bfloat16 h0, l0, h1, l1;
            split2(v0 * inv, h0, l0);
            split2(v1 * inv, h1, l1);
            g_aph[ob + i * 2]     = h0;
            g_aph[ob + i * 2 + 1] = h1;
            g_apl[ob + i * 2]     = l0;
            g_apl[ob + i * 2 + 1] = l1;
        }
    }
}

// ============================================================================
// SE gate (unchanged)
// ============================================================================
__global__ void se_kernel(const float* __restrict__ kp,
                          const float* __restrict__ se_w1, const float* __restrict__ se_b1,
                          const float* __restrict__ se_w2, const float* __restrict__ se_b2,
                          float* __restrict__ s_out) {
    const int i = blockIdx.x;
    const int w = blockIdx.y;
    __shared__ float pooled[DIMC];
    __shared__ float hsm[16];
    const int j = threadIdx.x;

    size_t base = (size_t)(i * TOK + w * 9) * DIMC + j;
    float p = 0.f;
#pragma unroll
    for (int tap = 0; tap < 9; tap++) p += kp[base + (size_t)tap * DIMC];
    pooled[j] = p * (1.f / 9.f);
    __syncthreads();

    if (j < 16) {
        float hv = se_b1[w * 16 + j];
        const float* w1 = se_w1 + (size_t)(w * 16 + j) * DIMC;
        for (int c = 0; c < DIMC; c++) hv += pooled[c] * w1[c];
        hsm[j] = fmaxf(hv, 0.f);
    }
    __syncthreads();

    float acc = se_b2[w * DIMC + j];
    const float* w2 = se_w2 + (size_t)(w * DIMC + j) * 16;
#pragma unroll
    for (int k = 0; k < 16; k++) acc += hsm[k] * w2[k];
    s_out[(size_t)(w * DIMC + i) * DIMC + j] = 1.f / (1.f + __expf(-acc));
}

// ============================================================================
// weight prep -> hi/lo planes  [((w*256+cout)*9+tap)*256 + cin]
// ============================================================================
__global__ void prep_w(const float* __restrict__ kp, const float* __restrict__ s) {
    int idx = blockIdx.x * 256 + threadIdx.x;
    int cin = idx & 255;
    int t2  = idx >> 8;
    int tap = t2 % 9;
    int t3  = t2 / 9;
    int cout = t3 & 255;
    int w    = t3 >> 8;
    float v = kp[(size_t)(cout * TOK + w * 9 + tap) * DIMC + cin]
            * s[(size_t)(w * DIMC + cout) * DIMC + cin];
    __nv_bfloat16 h, l;
    split2(v, h, l);
    g_wbh[idx] = h;
    g_wbl[idx] = l;
}

// ============================================================================
// grouped conv: warp-MMA bf16 implicit GEMM. M=256, N=128, K=2304.
// 512 threads / 16 warps (4m x 4n, warp tile 64 pos x 32 cout) -> 4 warps/SMSP.
// Triple-buffered B, fused hi/lo; per-acc order hh->hl->lh (bit-identical).
// ============================================================================
#define C_XSH 0
#define C_XSL 41472
#define C_BBASE 82944
#define C_BBUF  32768
#define C_SMEM  181248

__global__ void __launch_bounds__(512, 1)
conv_mma(float* __restrict__ y) {
    extern __shared__ char smem[];
    const uint32_t sb = smem_u32(smem);
    const int tid = threadIdx.x;
    const int lane = tid & 31;
    const int wid = tid >> 5;
    const int wm = wid & 3;            // 4 m-groups of 64 positions
    const int wn = wid >> 2;           // 4 n-groups of 32 couts
    const int nhalf = blockIdx.x;
    const int b = blockIdx.y;
    const int w = blockIdx.z;
    const int lm = lane & 15, kh = lane >> 4;
    const int quad = lane >> 2, qt = lane & 3;
    const int l7 = lane & 7;
    const int kbit = (lane >> 3) & 1;
    const int nloc = ((lane >> 4) << 3) | l7;
    const int wb = b * 16 + w;

    const __nv_bfloat16* wbh = g_wbh + ((size_t)(w * 256 + nhalf * 128) * 9) * 256;
    const __nv_bfloat16* wbl = g_wbl + ((size_t)(w * 256 + nhalf * 128) * 9) * 256;

    float acc[4][4][4] = {};   // [fm 0..3][fn 0..3][4]

    auto xsfill = [&](int chunk) {
        const size_t base = ((size_t)(wb * 4 + chunk)) * 324 * 64;
        const __nv_bfloat16* srcH = g_xth + base;
        const __nv_bfloat16* srcL = g_xtl + base;
        for (int i = tid; i < 5184; i += 512) {
            int plane = (i >= 2592);
            int j = i - plane * 2592;
            int r = j >> 3, q = j & 7;
            uint32_t dst = sb + (plane ? C_XSL : C_XSH) + r * 128 + ((q ^ (r & 7)) << 4);
            cp16(dst, (plane ? srcL : srcH) + r * 64 + q * 8);
        }
    };
    auto bfill = [&](int kt) {
        int nc = kt / 9, nt = kt - nc * 9;
        uint32_t d = sb + C_BBASE + (kt % 3) * C_BBUF;
        fill_tile512(d,         wbh + (size_t)nt * 256 + nc * 64, 2304, tid);
        fill_tile512(d + 16384, wbl + (size_t)nt * 256 + nc * 64, 2304, tid);
    };

    // prologue: xs(0), B(0), B(1)
    xsfill(0); CP_COMMIT();
    bfill(0);  CP_COMMIT();
    bfill(1);  CP_COMMIT();

#pragma unroll 1
    for (int kt = 0; kt < 36; kt++) {
        const int chunk = kt / 9;
        const int tap = kt - chunk * 9;
        if (tap == 0) {
            if (kt) {
                __syncthreads();        // prev chunk MMAs done -> xs overwrite safe
                xsfill(chunk); CP_COMMIT();
            }
            CP_WAIT0();
        } else {
            CP_WAIT1();
        }
        __syncthreads();
        if (kt + 2 < 36) {              // buf (kt+2)%3 was read at tap kt-1; safe after sync
            bfill(kt + 2); CP_COMMIT();
        }
        const uint32_t BbH = sb + C_BBASE + (kt % 3) * C_BBUF + (wn * 32 + nloc) * 128;
        const uint32_t BbL = BbH + 16384;

        const int ky = tap / 3, kx = tap - ky * 3;
        int arow[4];
#pragma unroll
        for (int fm = 0; fm < 4; fm++) {
            int p = wm * 64 + fm * 16 + lm;
            arow[fm] = ((p >> 4) + ky) * 18 + (p & 15) + kx;
        }

#pragma unroll
        for (int ks = 0; ks < 4; ks++) {
            uint32_t ah[4][4], al[4][4];
#pragma unroll
            for (int fm = 0; fm < 4; fm++) {
                uint32_t acol = (uint32_t)(((ks * 2 + kh) ^ (arow[fm] & 7)) << 4);
                ldsm4(ah[fm], sb + C_XSH + arow[fm] * 128 + acol);
                ldsm4(al[fm], sb + C_XSL + arow[fm] * 128 + acol);
            }
            const uint32_t bcol = (uint32_t)(((ks * 2 + kbit) ^ l7) << 4);
#pragma unroll
            for (int p = 0; p < 2; p++) {
                uint32_t bh[4], bl[4];
                ldsm4(bh, BbH + p * 2048 + bcol);
                ldsm4(bl, BbL + p * 2048 + bcol);
                // sweep hh (8 indep accs)
#pragma unroll
                for (int fm = 0; fm < 4; fm++) {
                    mma16816(acc[fm][2 * p],     ah[fm], bh);
                    mma16816(acc[fm][2 * p + 1], ah[fm], bh + 2);
                }
                // sweep hl
#pragma unroll
                for (int fm = 0; fm < 4; fm++) {
                    mma16816(acc[fm][2 * p],     ah[fm], bl);
                    mma16816(acc[fm][2 * p + 1], ah[fm], bl + 2);
                }
                // sweep lh
#pragma unroll
                for (int fm = 0; fm < 4; fm++) {
                    mma16816(acc[fm][2 * p],     al[fm], bh);
                    mma16816(acc[fm][2 * p + 1], al[fm], bh + 2);
                }
            }
        }
    }

    // ---- epilogue ----
    float* ybase = y + (size_t)((w * 16 + b) * 256) * 256 + nhalf * 128;
#pragma unroll
    for (int fm = 0; fm < 4; fm++) {
        int pos = wm * 64 + fm * 16 + quad;
#pragma unroll
        for (int fn = 0; fn < 4; fn++) {
            int col = wn * 32 + fn * 8 + qt * 2;
            float* c = acc[fm][fn];
            *(float2*)(ybase + (size_t)pos * 256 + col)       = make_float2(c[0], c[1]);
            *(float2*)(ybase + (size_t)(pos + 8) * 256 + col) = make_float2(c[2], c[3]);
        }
    }
}

// ============================================================================
// window reverse + channel LayerNorm + residual (unchanged)
// ============================================================================
__global__ void ln_kernel(const float* __restrict__ x, const float* __restrict__ y,
                          const float* __restrict__ ln_g, const float* __restrict__ ln_b,
                          float* __restrict__ out) {
    extern __shared__ float sm[];
    __shared__ float red[2][4][64];
    __shared__ float mu[64], rs[64];

    const int yy = blockIdx.x;
    const int b  = blockIdx.y;
    const int t  = threadIdx.x;
    const int hi = yy >> 4;
    const int py = yy & 15;

    for (int xx = 0; xx < 64; xx++) {
        int w = hi * 4 + (xx >> 4);
        int p = py * 16 + (xx & 15);
        sm[t * 65 + xx] = y[((size_t)((w * 16 + b) * 256 + p)) * DIMC + t];
    }
    __syncthreads();

    {
        int xx = t & 63, part = t >> 6;
        float s1 = 0.f, s2 = 0.f;
        for (int c = part * 64; c < part * 64 + 64; c++) {
            float v = sm[c * 65 + xx];
            s1 += v; s2 += v * v;
        }
        red[0][part][xx] = s1;
        red[1][part][xx] = s2;
    }
    __syncthreads();
    if (t < 64) {
        float S = 0.f, S2 = 0.f;
#pragma unroll
        for (int p2 = 0; p2 < 4; p2++) { S += red[0][p2][t]; S2 += red[1][p2][t]; }
        float m = S * (1.f / 256.f);
        float var = S2 * (1.f / 256.f) - m * m;
        mu[t] = m;
        rs[t] = rsqrtf(var + 1e-5f);
    }
    __syncthreads();

    for (int idx = t; idx < 256 * 64; idx += 256) {
        int c  = idx >> 6;
        int xi = idx & 63;
        float v = (sm[c * 65 + xi] - mu[xi]) * rs[xi] * ln_g[c] + ln_b[c];
        size_t oidx = ((size_t)(b * DIMC + c) * IMG + yy) * IMG + xi;
        out[oidx] = x[oidx] + v;
    }
}

// ============================================================================
// launch
// ============================================================================
extern "C" void kernel_launch(void* const* d_in, const int* in_sizes, int n_in,
                              void* d_out, int out_size) {
    const float* x      = (const float*)d_in[0];
    const float* conv_w = (const float*)d_in[1];
    const float* wqkv   = (const float*)d_in[2];
    const float* bqkv   = (const float*)d_in[3];
    const float* wout   = (const float*)d_in[4];
    const float* bout   = (const float*)d_in[5];
    const float* se_w1  = (const float*)d_in[6];
    const float* se_b1  = (const float*)d_in[7];
    const float* se_w2  = (const float*)d_in[8];
    const float* se_b2  = (const float*)d_in[9];
    const float* ln_g   = (const float*)d_in[10];
    const float* ln_b   = (const float*)d_in[11];
    float* out = (float*)d_out;

    float *qkvb, *kpb, *sbuf, *yb;
    __nv_bfloat16 *aph, *apl, *bqh, *bql, *bwh, *bwl;
    cudaGetSymbolAddress((void**)&qkvb, g_qkv);
    cudaGetSymbolAddress((void**)&kpb,  g_kp);
    cudaGetSymbolAddress((void**)&sbuf, g_s);
    cudaGetSymbolAddress((void**)&yb,   g_y);
    cudaGetSymbolAddress((void**)&aph,  g_aph);
    cudaGetSymbolAddress((void**)&apl,  g_apl);
    cudaGetSymbolAddress((void**)&bqh,  g_bqh);
    cudaGetSymbolAddress((void**)&bql,  g_bql);
    cudaGetSymbolAddress((void**)&bwh,  g_bwh);
    cudaGetSymbolAddress((void**)&bwl,  g_bwl);

    cudaFuncSetAttribute(conv_mma, cudaFuncAttributeMaxDynamicSharedMemorySize, C_SMEM);
    cudaFuncSetAttribute(gemm_mma, cudaFuncAttributeMaxDynamicSharedMemorySize, G_SMEM);
    cudaFuncSetAttribute(pack_x, cudaFuncAttributeMaxDynamicSharedMemorySize,
                         64 * 325 * (int)sizeof(float));
    cudaFuncSetAttribute(ln_kernel, cudaFuncAttributeMaxDynamicSharedMemorySize,
                         256 * 65 * (int)sizeof(float));

    // pack weights
    pack_bt<<<3 * DIMC, 256>>>(wqkv, bqh, bql, 3 * DIMC);
    pack_bt<<<DIMC, 256>>>(wout, bwh, bwl, DIMC);

    // kt planes from conv_w (tiled transpose)
    build_kt_tr<<<dim3(256, 4), 256>>>(conv_w);

    // qkv = kt @ wqkv + bqkv
    gemm_mma<<<dim3(6, MROWS / 128), 256, G_SMEM>>>(aph, apl, bqh, bql, bqkv, qkvb, 3 * DIMC);

    // x windows pack (independent; only needed before conv)
    pack_x<<<BATCH * WN, 256, 64 * 325 * sizeof(float)>>>(x);

    // attention (writes A planes for wout gemm)
    attn_kernel<<<dim3(DIMC, HEADS), 160>>>(qkvb);

    // kp = o @ wout + bout
    gemm_mma<<<dim3(2, MROWS / 128), 256, G_SMEM>>>(aph, apl, bwh, bwl, bout, kpb, DIMC);

    // SE gate
    se_kernel<<<dim3(DIMC, WN), 256>>>(kpb, se_w1, se_b1, se_w2, se_b2, sbuf);

    // gated weight planes
    prep_w<<<WN * DIMC * 9, 256>>>(kpb, sbuf);

    // grouped conv on tensor cores (512 threads, 16 warps)
    conv_mma<<<dim3(2, BATCH, WN), 512, C_SMEM>>>(yb);

    // window reverse + LN + residual
    ln_kernel<<<dim3(IMG, BATCH), 256, 256 * 65 * sizeof(float)>>>(x, yb, ln_g, ln_b, out);
}

// round 13
// speedup vs baseline: 1.1502x; 1.1502x over previous
#include <cuda_runtime.h>
#include <cuda_bf16.h>
#include <cuda_fp16.h>
#include <stdint.h>
#include <math.h>

// ---------------- problem constants ----------------
#define DIMC   256
#define HEADS  8
#define HD     32
#define WSZ    16
#define WN     16
#define KS     3
#define BATCH  16
#define IMG    64
#define TOK    144
#define MROWS  36864               // DIMC*TOK

// ---------------- scratch ----------------
__device__ float          g_qkv[MROWS * 3 * DIMC];
__device__ float          g_kp [MROWS * DIMC];
__device__ float          g_s  [WN * DIMC * DIMC];
__device__ float          g_y  [WN * BATCH * 256 * DIMC];   // (w,b,pos,cout)
__device__ __nv_bfloat16  g_aph[MROWS * DIMC];              // A hi plane (kt, then attn-o)
__device__ __nv_bfloat16  g_apl[MROWS * DIMC];              // A lo plane
__device__ __nv_bfloat16  g_bqh[3 * DIMC * DIMC];           // wqkv^T hi [n][k]
__device__ __nv_bfloat16  g_bql[3 * DIMC * DIMC];
__device__ __nv_bfloat16  g_bwh[DIMC * DIMC];               // wout^T hi [n][k]
__device__ __nv_bfloat16  g_bwl[DIMC * DIMC];
__device__ __half         g_wfh[WN * DIMC * 9 * DIMC];      // gated conv W fp16 hi [w][cout][tap][cin]
__device__ __half         g_wfl[WN * DIMC * 9 * DIMC];      // fp16 lo
__device__ __half         g_xf [BATCH * WN * 4 * 324 * 64]; // x windows fp16 [(b*16+w)*4+chunk][row][cin64]

// ============================================================================
// helpers
// ============================================================================
__device__ __forceinline__ uint32_t smem_u32(const void* p) {
    uint32_t a;
    asm("{ .reg .u64 t; cvta.to.shared.u64 t, %1; cvt.u32.u64 %0, t; }" : "=r"(a) : "l"(p));
    return a;
}
__device__ __forceinline__ void split2(float v, __nv_bfloat16& h, __nv_bfloat16& l) {
    h = __float2bfloat16(v);
    l = __float2bfloat16(v - __bfloat162float(h));
}
__device__ __forceinline__ void mma16816(float* d, const uint32_t* a, const uint32_t* b) {
    asm volatile("mma.sync.aligned.m16n8k16.row.col.f32.bf16.bf16.f32 "
        "{%0,%1,%2,%3}, {%4,%5,%6,%7}, {%8,%9}, {%0,%1,%2,%3};"
        : "+f"(d[0]), "+f"(d[1]), "+f"(d[2]), "+f"(d[3])
        : "r"(a[0]), "r"(a[1]), "r"(a[2]), "r"(a[3]), "r"(b[0]), "r"(b[1]));
}
__device__ __forceinline__ void mma16816h(float* d, const uint32_t* a, const uint32_t* b) {
    asm volatile("mma.sync.aligned.m16n8k16.row.col.f32.f16.f16.f32 "
        "{%0,%1,%2,%3}, {%4,%5,%6,%7}, {%8,%9}, {%0,%1,%2,%3};"
        : "+f"(d[0]), "+f"(d[1]), "+f"(d[2]), "+f"(d[3])
        : "r"(a[0]), "r"(a[1]), "r"(a[2]), "r"(a[3]), "r"(b[0]), "r"(b[1]));
}
__device__ __forceinline__ void ldsm4(uint32_t* r, uint32_t addr) {
    asm volatile("ldmatrix.sync.aligned.m8n8.x4.shared.b16 {%0,%1,%2,%3}, [%4];"
        : "=r"(r[0]), "=r"(r[1]), "=r"(r[2]), "=r"(r[3]) : "r"(addr));
}
__device__ __forceinline__ void cp16(uint32_t dst, const void* src) {
    asm volatile("cp.async.cg.shared.global [%0], [%1], 16;" :: "r"(dst), "l"(src));
}
#define CP_COMMIT() asm volatile("cp.async.commit_group;" ::: "memory")
#define CP_WAIT0()  asm volatile("cp.async.wait_group 0;" ::: "memory")
#define CP_WAIT1()  asm volatile("cp.async.wait_group 1;" ::: "memory")

// packed f32x2 (Blackwell): one instr = two independent fp32 FMAs
typedef unsigned long long u64p;
__device__ __forceinline__ u64p pk2(float lo, float hi) {
    u64p r; asm("mov.b64 %0, {%1, %2};" : "=l"(r) : "f"(lo), "f"(hi)); return r;
}
__device__ __forceinline__ void up2(u64p v, float& lo, float& hi) {
    asm("mov.b64 {%0, %1}, %2;" : "=f"(lo), "=f"(hi) : "l"(v));
}
__device__ __forceinline__ void ffma2(u64p& d, u64p a, u64p b) {
    asm("fma.rn.f32x2 %0, %1, %2, %0;" : "+l"(d) : "l"(a), "l"(b));
}

// Fill a 128x64-elem (16-bit) tile (XOR-swizzled 128B rows) via cp.async.
template <typename T>
__device__ __forceinline__ void fill_tile256(uint32_t dst, const T* src,
                                             int rstride, int tid) {
#pragma unroll
    for (int i = 0; i < 4; i++) {
        int idx = tid + i * 256;
        int r = idx >> 3, q = idx & 7;
        cp16(dst + r * 128 + ((q ^ (r & 7)) << 4), src + (size_t)r * rstride + q * 8);
    }
}

// ============================================================================
// pack kernels
// ============================================================================
__global__ void build_kt_tr(const float* __restrict__ conv_w) {
    __shared__ float sm[64][145];
    const int tid = threadIdx.x;
    const int c1 = blockIdx.x;
    const int cc0 = blockIdx.y * 64;
    const int w = c1 & 15, b = c1 >> 4;
    const float* src = conv_w + ((size_t)(w * 16 + b) * 256 + cc0) * 144;
    for (int idx = tid; idx < 64 * 144; idx += 256) {
        int c = idx / 144, l = idx - c * 144;
        sm[c][l] = src[c * 144 + l];
    }
    __syncthreads();
    for (int idx = tid; idx < 144 * 64; idx += 256) {
        int l = idx >> 6, c = idx & 63;
        __nv_bfloat16 h, lo;
        split2(sm[c][l], h, lo);
        size_t o = (size_t)(c1 * 144 + l) * 256 + cc0 + c;
        g_aph[o] = h;
        g_apl[o] = lo;
    }
}
__global__ void pack_bt(const float* __restrict__ W, __nv_bfloat16* __restrict__ oh,
                        __nv_bfloat16* __restrict__ ol, int N) {
    int idx = blockIdx.x * 256 + threadIdx.x;
    int k = idx & 255;
    int n = idx >> 8;
    __nv_bfloat16 h, l;
    split2(W[(size_t)k * N + n], h, l);
    oh[idx] = h;
    ol[idx] = l;
}
// x windows -> single fp16 plane [(b*16+w)*4+chunk][row=yy*18+xx][cin64]
__global__ void pack_x(const float* __restrict__ x) {
    extern __shared__ float sm[];        // [64][325]
    const int tid = threadIdx.x;
    const int wb = blockIdx.x;           // b*16 + w
    const int b = wb >> 4, w = wb & 15;
    const int h0 = (w >> 2) * WSZ;
    const int w0 = (w & 3) * WSZ;
    for (int chunk = 0; chunk < 4; chunk++) {
        const int c0 = chunk * 64;
        __syncthreads();
        for (int i = tid; i < 64 * 324; i += 256) {
            int ci = i / 324;
            int rem = i - ci * 324;
            int yy = rem / 18;
            int xx = rem - yy * 18;
            float v = 0.f;
            if ((unsigned)(yy - 1) < 16u && (unsigned)(xx - 1) < 16u)
                v = x[((size_t)(b * DIMC + c0 + ci) * IMG + h0 + yy - 1) * IMG + w0 + xx - 1];
            sm[ci * 325 + rem] = v;
        }
        __syncthreads();
        size_t obase = ((size_t)(wb * 4 + chunk)) * 324 * 64;
        for (int i = tid; i < 324 * 64; i += 256) {
            int row = i >> 6, ci = i & 63;
            g_xf[obase + i] = __float2half_rn(sm[ci * 325 + row]);
        }
    }
}

// ============================================================================
// GEMM: C[M,N] = A @ B^T + bias, K=256 (unchanged from R11 best: bf16 3-pass).
// ============================================================================
#define G_AH 0
#define G_AL 16384
#define G_BH 32768
#define G_BL 49152
#define G_SMEM 65536

__global__ void __launch_bounds__(256, 2)
gemm_mma(const __nv_bfloat16* __restrict__ Ah, const __nv_bfloat16* __restrict__ Al,
         const __nv_bfloat16* __restrict__ Bh, const __nv_bfloat16* __restrict__ Bl,
         const float* __restrict__ bias, float* __restrict__ C, int N) {
    extern __shared__ char smem[];
    const uint32_t sb = smem_u32(smem);
    const int tid = threadIdx.x;
    const int lane = tid & 31;
    const int wid = tid >> 5;
    const int wm = wid & 3, wn = wid >> 2;
    const int m0 = blockIdx.y * 128, n0 = blockIdx.x * 128;
    const int lm = lane & 15, kh = lane >> 4;
    const int quad = lane >> 2, qt = lane & 3;
    const int l7 = lane & 7;
    const int kbit = (lane >> 3) & 1;
    const int nloc = ((lane >> 4) << 3) | l7;

    float acc[2][8][4] = {};

#pragma unroll 1
    for (int kc = 0; kc < 4; kc++) {
        const int k0 = kc * 64;
        fill_tile256(sb + G_AH, Ah + (size_t)m0 * 256 + k0, 256, tid);
        fill_tile256(sb + G_AL, Al + (size_t)m0 * 256 + k0, 256, tid);
        fill_tile256(sb + G_BH, Bh + (size_t)n0 * 256 + k0, 256, tid);
        fill_tile256(sb + G_BL, Bl + (size_t)n0 * 256 + k0, 256, tid);
        CP_COMMIT();
        CP_WAIT0();
        __syncthreads();

        const uint32_t AbH = sb + G_AH;
        const uint32_t AbL = sb + G_AL;
        const uint32_t BbH = sb + G_BH + (wn * 64 + nloc) * 128;
        const uint32_t BbL = sb + G_BL + (wn * 64 + nloc) * 128;
#pragma unroll
        for (int ks = 0; ks < 4; ks++) {
            uint32_t ah[2][4], al[2][4];
#pragma unroll
            for (int fm = 0; fm < 2; fm++) {
                int m = wm * 32 + fm * 16 + lm;
                uint32_t acol = (uint32_t)(((ks * 2 + kh) ^ (lm & 7)) << 4);
                ldsm4(ah[fm], AbH + m * 128 + acol);
                ldsm4(al[fm], AbL + m * 128 + acol);
            }
            const uint32_t bcol = (uint32_t)(((ks * 2 + kbit) ^ l7) << 4);
            uint32_t bh[4][4], bl[4][4];
#pragma unroll
            for (int p = 0; p < 4; p++) {
                ldsm4(bh[p], BbH + p * 2048 + bcol);
                ldsm4(bl[p], BbL + p * 2048 + bcol);
            }
#pragma unroll
            for (int p = 0; p < 4; p++)
#pragma unroll
                for (int fm = 0; fm < 2; fm++) {
                    mma16816(acc[fm][2 * p],     ah[fm], bh[p]);
                    mma16816(acc[fm][2 * p + 1], ah[fm], bh[p] + 2);
                }
#pragma unroll
            for (int p = 0; p < 4; p++)
#pragma unroll
                for (int fm = 0; fm < 2; fm++) {
                    mma16816(acc[fm][2 * p],     ah[fm], bl[p]);
                    mma16816(acc[fm][2 * p + 1], ah[fm], bl[p] + 2);
                }
#pragma unroll
            for (int p = 0; p < 4; p++)
#pragma unroll
                for (int fm = 0; fm < 2; fm++) {
                    mma16816(acc[fm][2 * p],     al[fm], bh[p]);
                    mma16816(acc[fm][2 * p + 1], al[fm], bh[p] + 2);
                }
        }
        __syncthreads();
    }

#pragma unroll
    for (int fm = 0; fm < 2; fm++) {
        int m = m0 + wm * 32 + fm * 16 + quad;
#pragma unroll
        for (int fn = 0; fn < 8; fn++) {
            int col = n0 + wn * 64 + fn * 8 + qt * 2;
            float b0 = bias[col], b1 = bias[col + 1];
            float* c = acc[fm][fn];
            *(float2*)&C[(size_t)m * N + col]       = make_float2(c[0] + b0, c[1] + b1);
            *(float2*)&C[(size_t)(m + 8) * N + col] = make_float2(c[2] + b0, c[3] + b1);
        }
    }
}

// ============================================================================
// attention — single pass, packed f32x2 FMA (unchanged from R11)
// ============================================================================
__global__ void attn_kernel(const float* __restrict__ qkv) {
    const int c1 = blockIdx.x;
    const int h  = blockIdx.y;
    __shared__ float ks[TOK][HD];
    __shared__ float vs[TOK][HD];

    for (int idx = threadIdx.x; idx < TOK * HD; idx += blockDim.x) {
        int t = idx >> 5, e = idx & 31;
        size_t base = (size_t)(c1 * TOK + t) * 768 + h * HD + e;
        ks[t][e] = qkv[base + 256];
        vs[t][e] = qkv[base + 512];
    }
    __syncthreads();

    const int t = threadIdx.x;
    if (t < TOK) {
        const float scale = 0.17677669529663687f;
        u64p q2[16];
        {
            const float2* qsrc = (const float2*)(qkv + (size_t)(c1 * TOK + t) * 768 + h * HD);
#pragma unroll
            for (int i = 0; i < 16; i++) {
                float2 v = qsrc[i];
                q2[i] = pk2(v.x * scale, v.y * scale);
            }
        }

        u64p a2[16];
#pragma unroll
        for (int i = 0; i < 16; i++) a2[i] = pk2(0.f, 0.f);
        float denom = 0.f;

        for (int j = 0; j < TOK; j++) {
            const u64p* k2 = (const u64p*)ks[j];
            u64p s0 = pk2(0.f, 0.f), s1 = s0, s2 = s0, s3 = s0;
#pragma unroll
            for (int i = 0; i < 16; i += 4) {
                ffma2(s0, q2[i],     k2[i]);
                ffma2(s1, q2[i + 1], k2[i + 1]);
                ffma2(s2, q2[i + 2], k2[i + 2]);
                ffma2(s3, q2[i + 3], k2[i + 3]);
            }
            float x0, x1, y0, y1, z0, z1, w0, w1;
            up2(s0, x0, x1); up2(s1, y0, y1); up2(s2, z0, z1); up2(s3, w0, w1);
            float sc = ((x0 + x1) + (y0 + y1)) + ((z0 + z1) + (w0 + w1));
            float pexp = __expf(sc);
            denom += pexp;
            u64p pe2 = pk2(pexp, pexp);
            const u64p* v2 = (const u64p*)vs[j];
#pragma unroll
            for (int i = 0; i < 16; i++) ffma2(a2[i], pe2, v2[i]);
        }
        float inv = 1.f / denom;
        size_t ob = (size_t)(c1 * TOK + t) * DIMC + h * HD;
#pragma unroll
        for (int i = 0; i < 16; i++) {
            float v0, v1;
            up2(a2[i], v0, v1);
            __nv_bfloat16 h0, l0, h1, l1;
            split2(v0 * inv, h0, l0);
            split2(v1 * inv, h1, l1);
            g_aph[ob + i * 2]     = h0;
            g_aph[ob + i * 2 + 1] = h1;
            g_apl[ob + i * 2]     = l0;
            g_apl[ob + i * 2 + 1] = l1;
        }
    }
}

// ============================================================================
// SE gate (unchanged)
// ============================================================================
__global__ void se_kernel(const float* __restrict__ kp,
                          const float* __restrict__ se_w1, const float* __restrict__ se_b1,
                          const float* __restrict__ se_w2, const float* __restrict__ se_b2,
                          float* __restrict__ s_out) {
    const int i = blockIdx.x;
    const int w = blockIdx.y;
    __shared__ float pooled[DIMC];
    __shared__ float hsm[16];
    const int j = threadIdx.x;

    size_t base = (size_t)(i * TOK + w * 9) * DIMC + j;
    float p = 0.f;
#pragma unroll
    for (int tap = 0; tap < 9; tap++) p += kp[base + (size_t)tap * DIMC];
    pooled[j] = p * (1.f / 9.f);
    __syncthreads();

    if (j < 16) {
        float hv = se_b1[w * 16 + j];
        const float* w1 = se_w1 + (size_t)(w * 16 + j) * DIMC;
        for (int c = 0; c < DIMC; c++) hv += pooled[c] * w1[c];
        hsm[j] = fmaxf(hv, 0.f);
    }
    __syncthreads();

    float acc = se_b2[w * DIMC + j];
    const float* w2 = se_w2 + (size_t)(w * DIMC + j) * 16;
#pragma unroll
    for (int k = 0; k < 16; k++) acc += hsm[k] * w2[k];
    s_out[(size_t)(w * DIMC + i) * DIMC + j] = 1.f / (1.f + __expf(-acc));
}

// ============================================================================
// weight prep -> fp16 hi/lo planes  [((w*256+cout)*9+tap)*256 + cin]
// ============================================================================
__global__ void prep_w(const float* __restrict__ kp, const float* __restrict__ s) {
    int idx = blockIdx.x * 256 + threadIdx.x;
    int cin = idx & 255;
    int t2  = idx >> 8;
    int tap = t2 % 9;
    int t3  = t2 / 9;
    int cout = t3 & 255;
    int w    = t3 >> 8;
    float v = kp[(size_t)(cout * TOK + w * 9 + tap) * DIMC + cin]
            * s[(size_t)(w * DIMC + cout) * DIMC + cin];
    __half h = __float2half_rn(v);
    __half l = __float2half_rn(v - __half2float(h));
    g_wfh[idx] = h;
    g_wfl[idx] = l;
}

// ============================================================================
// grouped conv: warp-MMA fp16 implicit GEMM, 2-pass (A single, W hi/lo).
// M=256, N=128, K=2304. 256 threads / 8 warps (R11 shape).
// Triple-buffered B; xs single fp16 plane.
// smem: XS 41472 | 3 x B 32768 = 139776 B.
// ============================================================================
#define C_XS 0
#define C_BBASE 41472
#define C_BBUF  32768
#define C_SMEM  139776

__global__ void __launch_bounds__(256, 1)
conv_mma(float* __restrict__ y) {
    extern __shared__ char smem[];
    const uint32_t sb = smem_u32(smem);
    const int tid = threadIdx.x;
    const int lane = tid & 31;
    const int wid = tid >> 5;
    const int wm = wid & 3, wn = wid >> 2;
    const int nhalf = blockIdx.x;
    const int b = blockIdx.y;
    const int w = blockIdx.z;
    const int lm = lane & 15, kh = lane >> 4;
    const int quad = lane >> 2, qt = lane & 3;
    const int l7 = lane & 7;
    const int kbit = (lane >> 3) & 1;
    const int nloc = ((lane >> 4) << 3) | l7;
    const int wb = b * 16 + w;

    const __half* wfh = g_wfh + ((size_t)(w * 256 + nhalf * 128) * 9) * 256;
    const __half* wfl = g_wfl + ((size_t)(w * 256 + nhalf * 128) * 9) * 256;

    float acc[4][8][4] = {};

    auto xsfill = [&](int chunk) {
        const __half* src = g_xf + ((size_t)(wb * 4 + chunk)) * 324 * 64;
        for (int i = tid; i < 2592; i += 256) {
            int r = i >> 3, q = i & 7;
            uint32_t dst = sb + C_XS + r * 128 + ((q ^ (r & 7)) << 4);
            cp16(dst, src + r * 64 + q * 8);
        }
    };
    auto bfill = [&](int kt) {
        int nc = kt / 9, nt = kt - nc * 9;
        uint32_t d = sb + C_BBASE + (kt % 3) * C_BBUF;
        fill_tile256(d,         wfh + (size_t)nt * 256 + nc * 64, 2304, tid);
        fill_tile256(d + 16384, wfl + (size_t)nt * 256 + nc * 64, 2304, tid);
    };

    // prologue: xs(0), B(0), B(1)
    xsfill(0); CP_COMMIT();
    bfill(0);  CP_COMMIT();
    bfill(1);  CP_COMMIT();

#pragma unroll 1
    for (int kt = 0; kt < 36; kt++) {
        const int chunk = kt / 9;
        const int tap = kt - chunk * 9;
        if (tap == 0) {
            if (kt) {
                __syncthreads();        // prev chunk MMAs done -> xs overwrite safe
                xsfill(chunk); CP_COMMIT();
            }
            CP_WAIT0();
        } else {
            CP_WAIT1();
        }
        __syncthreads();
        if (kt + 2 < 36) {              // buf (kt+2)%3 was read at tap kt-1; safe after sync
            bfill(kt + 2); CP_COMMIT();
        }
        const uint32_t BbH = sb + C_BBASE + (kt % 3) * C_BBUF + (wn * 64 + nloc) * 128;
        const uint32_t BbL = BbH + 16384;

        const int ky = tap / 3, kx = tap - ky * 3;
        int arow[4];
#pragma unroll
        for (int fm = 0; fm < 4; fm++) {
            int p = wm * 64 + fm * 16 + lm;
            arow[fm] = ((p >> 4) + ky) * 18 + (p & 15) + kx;
        }

#pragma unroll
        for (int ks = 0; ks < 4; ks++) {
            uint32_t a[4][4];
#pragma unroll
            for (int fm = 0; fm < 4; fm++) {
                uint32_t acol = (uint32_t)(((ks * 2 + kh) ^ (arow[fm] & 7)) << 4);
                ldsm4(a[fm], sb + C_XS + arow[fm] * 128 + acol);
            }
            const uint32_t bcol = (uint32_t)(((ks * 2 + kbit) ^ l7) << 4);
            uint32_t bh[4][4], bl[4][4];
#pragma unroll
            for (int p = 0; p < 4; p++) {
                ldsm4(bh[p], BbH + p * 2048 + bcol);
                ldsm4(bl[p], BbL + p * 2048 + bcol);
            }
            // sweep 1: A * Wh  (32 independent accumulators)
#pragma unroll
            for (int p = 0; p < 4; p++)
#pragma unroll
                for (int fm = 0; fm < 4; fm++) {
                    mma16816h(acc[fm][2 * p],     a[fm], bh[p]);
                    mma16816h(acc[fm][2 * p + 1], a[fm], bh[p] + 2);
                }
            // sweep 2: A * Wl
#pragma unroll
            for (int p = 0; p < 4; p++)
#pragma unroll
                for (int fm = 0; fm < 4; fm++) {
                    mma16816h(acc[fm][2 * p],     a[fm], bl[p]);
                    mma16816h(acc[fm][2 * p + 1], a[fm], bl[p] + 2);
                }
        }
    }

    // ---- epilogue ----
    float* ybase = y + (size_t)((w * 16 + b) * 256) * 256 + nhalf * 128;
#pragma unroll
    for (int fm = 0; fm < 4; fm++) {
        int pos = wm * 64 + fm * 16 + quad;
#pragma unroll
        for (int fn = 0; fn < 8; fn++) {
            int col = wn * 64 + fn * 8 + qt * 2;
            float* c = acc[fm][fn];
            *(float2*)(ybase + (size_t)pos * 256 + col)       = make_float2(c[0], c[1]);
            *(float2*)(ybase + (size_t)(pos + 8) * 256 + col) = make_float2(c[2], c[3]);
        }
    }
}

// ============================================================================
// window reverse + channel LayerNorm + residual (unchanged)
// ============================================================================
__global__ void ln_kernel(const float* __restrict__ x, const float* __restrict__ y,
                          const float* __restrict__ ln_g, const float* __restrict__ ln_b,
                          float* __restrict__ out) {
    extern __shared__ float sm[];
    __shared__ float red[2][4][64];
    __shared__ float mu[64], rs[64];

    const int yy = blockIdx.x;
    const int b  = blockIdx.y;
    const int t  = threadIdx.x;
    const int hi = yy >> 4;
    const int py = yy & 15;

    for (int xx = 0; xx < 64; xx++) {
        int w = hi * 4 + (xx >> 4);
        int p = py * 16 + (xx & 15);
        sm[t * 65 + xx] = y[((size_t)((w * 16 + b) * 256 + p)) * DIMC + t];
    }
    __syncthreads();

    {
        int xx = t & 63, part = t >> 6;
        float s1 = 0.f, s2 = 0.f;
        for (int c = part * 64; c < part * 64 + 64; c++) {
            float v = sm[c * 65 + xx];
            s1 += v; s2 += v * v;
        }
        red[0][part][xx] = s1;
        red[1][part][xx] = s2;
    }
    __syncthreads();
    if (t < 64) {
        float S = 0.f, S2 = 0.f;
#pragma unroll
        for (int p2 = 0; p2 < 4; p2++) { S += red[0][p2][t]; S2 += red[1][p2][t]; }
        float m = S * (1.f / 256.f);
        float var = S2 * (1.f / 256.f) - m * m;
        mu[t] = m;
        rs[t] = rsqrtf(var + 1e-5f);
    }
    __syncthreads();

    for (int idx = t; idx < 256 * 64; idx += 256) {
        int c  = idx >> 6;
        int xi = idx & 63;
        float v = (sm[c * 65 + xi] - mu[xi]) * rs[xi] * ln_g[c] + ln_b[c];
        size_t oidx = ((size_t)(b * DIMC + c) * IMG + yy) * IMG + xi;
        out[oidx] = x[oidx] + v;
    }
}

// ============================================================================
// launch
// ============================================================================
extern "C" void kernel_launch(void* const* d_in, const int* in_sizes, int n_in,
                              void* d_out, int out_size) {
    const float* x      = (const float*)d_in[0];
    const float* conv_w = (const float*)d_in[1];
    const float* wqkv   = (const float*)d_in[2];
    const float* bqkv   = (const float*)d_in[3];
    const float* wout   = (const float*)d_in[4];
    const float* bout   = (const float*)d_in[5];
    const float* se_w1  = (const float*)d_in[6];
    const float* se_b1  = (const float*)d_in[7];
    const float* se_w2  = (const float*)d_in[8];
    const float* se_b2  = (const float*)d_in[9];
    const float* ln_g   = (const float*)d_in[10];
    const float* ln_b   = (const float*)d_in[11];
    float* out = (float*)d_out;

    float *qkvb, *kpb, *sbuf, *yb;
    __nv_bfloat16 *aph, *apl, *bqh, *bql, *bwh, *bwl;
    cudaGetSymbolAddress((void**)&qkvb, g_qkv);
    cudaGetSymbolAddress((void**)&kpb,  g_kp);
    cudaGetSymbolAddress((void**)&sbuf, g_s);
    cudaGetSymbolAddress((void**)&yb,   g_y);
    cudaGetSymbolAddress((void**)&aph,  g_aph);
    cudaGetSymbolAddress((void**)&apl,  g_apl);
    cudaGetSymbolAddress((void**)&bqh,  g_bqh);
    cudaGetSymbolAddress((void**)&bql,  g_bql);
    cudaGetSymbolAddress((void**)&bwh,  g_bwh);
    cudaGetSymbolAddress((void**)&bwl,  g_bwl);

    cudaFuncSetAttribute(conv_mma, cudaFuncAttributeMaxDynamicSharedMemorySize, C_SMEM);
    cudaFuncSetAttribute(gemm_mma, cudaFuncAttributeMaxDynamicSharedMemorySize, G_SMEM);
    cudaFuncSetAttribute(pack_x, cudaFuncAttributeMaxDynamicSharedMemorySize,
                         64 * 325 * (int)sizeof(float));
    cudaFuncSetAttribute(ln_kernel, cudaFuncAttributeMaxDynamicSharedMemorySize,
                         256 * 65 * (int)sizeof(float));

    // pack weights
    pack_bt<<<3 * DIMC, 256>>>(wqkv, bqh, bql, 3 * DIMC);
    pack_bt<<<DIMC, 256>>>(wout, bwh, bwl, DIMC);

    // kt planes from conv_w (tiled transpose)
    build_kt_tr<<<dim3(256, 4), 256>>>(conv_w);

    // qkv = kt @ wqkv + bqkv
    gemm_mma<<<dim3(6, MROWS / 128), 256, G_SMEM>>>(aph, apl, bqh, bql, bqkv, qkvb, 3 * DIMC);

    // x windows pack (independent; only needed before conv)
    pack_x<<<BATCH * WN, 256, 64 * 325 * sizeof(float)>>>(x);

    // attention (writes A planes for wout gemm)
    attn_kernel<<<dim3(DIMC, HEADS), 160>>>(qkvb);

    // kp = o @ wout + bout
    gemm_mma<<<dim3(2, MROWS / 128), 256, G_SMEM>>>(aph, apl, bwh, bwl, bout, kpb, DIMC);

    // SE gate
    se_kernel<<<dim3(DIMC, WN), 256>>>(kpb, se_w1, se_b1, se_w2, se_b2, sbuf);

    // gated weight fp16 planes
    prep_w<<<WN * DIMC * 9, 256>>>(kpb, sbuf);

    // grouped conv on tensor cores (fp16 2-pass)
    conv_mma<<<dim3(2, BATCH, WN), 256, C_SMEM>>>(yb);

    // window reverse + LN + residual
    ln_kernel<<<dim3(IMG, BATCH), 256, 256 * 65 * sizeof(float)>>>(x, yb, ln_g, ln_b, out);
}

// round 15
// speedup vs baseline: 1.1518x; 1.0014x over previous
#include <cuda_runtime.h>
#include <cuda_bf16.h>
#include <cuda_fp16.h>
#include <stdint.h>
#include <math.h>

// ---------------- problem constants ----------------
#define DIMC   256
#define HEADS  8
#define HD     32
#define WSZ    16
#define WN     16
#define KS     3
#define BATCH  16
#define IMG    64
#define TOK    144
#define MROWS  36864               // DIMC*TOK

// ---------------- scratch ----------------
__device__ float          g_qkv[MROWS * 3 * DIMC];
__device__ float          g_kp [MROWS * DIMC];
__device__ float          g_s  [WN * DIMC * DIMC];
__device__ float          g_y  [WN * BATCH * 256 * DIMC];   // (w,b,pos,cout)
__device__ __nv_bfloat16  g_aph[MROWS * DIMC];              // A hi plane (kt, then attn-o)
__device__ __nv_bfloat16  g_apl[MROWS * DIMC];              // A lo plane
__device__ __nv_bfloat16  g_bqh[3 * DIMC * DIMC];           // wqkv^T hi [n][k]
__device__ __nv_bfloat16  g_bql[3 * DIMC * DIMC];
__device__ __nv_bfloat16  g_bwh[DIMC * DIMC];               // wout^T hi [n][k]
__device__ __nv_bfloat16  g_bwl[DIMC * DIMC];
__device__ __half         g_wfh[WN * DIMC * 9 * DIMC];      // gated conv W fp16 hi [w][cout][tap][cin]
__device__ __half         g_wfl[WN * DIMC * 9 * DIMC];      // fp16 lo
__device__ __half         g_xf [BATCH * WN * 4 * 324 * 64]; // x windows fp16 [(b*16+w)*4+chunk][row][cin64]

// ============================================================================
// helpers
// ============================================================================
__device__ __forceinline__ uint32_t smem_u32(const void* p) {
    uint32_t a;
    asm("{ .reg .u64 t; cvta.to.shared.u64 t, %1; cvt.u32.u64 %0, t; }" : "=r"(a) : "l"(p));
    return a;
}
__device__ __forceinline__ void split2(float v, __nv_bfloat16& h, __nv_bfloat16& l) {
    h = __float2bfloat16(v);
    l = __float2bfloat16(v - __bfloat162float(h));
}
__device__ __forceinline__ void mma16816(float* d, const uint32_t* a, const uint32_t* b) {
    asm volatile("mma.sync.aligned.m16n8k16.row.col.f32.bf16.bf16.f32 "
        "{%0,%1,%2,%3}, {%4,%5,%6,%7}, {%8,%9}, {%0,%1,%2,%3};"
        : "+f"(d[0]), "+f"(d[1]), "+f"(d[2]), "+f"(d[3])
        : "r"(a[0]), "r"(a[1]), "r"(a[2]), "r"(a[3]), "r"(b[0]), "r"(b[1]));
}
__device__ __forceinline__ void mma16816h(float* d, const uint32_t* a, const uint32_t* b) {
    asm volatile("mma.sync.aligned.m16n8k16.row.col.f32.f16.f16.f32 "
        "{%0,%1,%2,%3}, {%4,%5,%6,%7}, {%8,%9}, {%0,%1,%2,%3};"
        : "+f"(d[0]), "+f"(d[1]), "+f"(d[2]), "+f"(d[3])
        : "r"(a[0]), "r"(a[1]), "r"(a[2]), "r"(a[3]), "r"(b[0]), "r"(b[1]));
}
__device__ __forceinline__ void ldsm4(uint32_t* r, uint32_t addr) {
    asm volatile("ldmatrix.sync.aligned.m8n8.x4.shared.b16 {%0,%1,%2,%3}, [%4];"
        : "=r"(r[0]), "=r"(r[1]), "=r"(r[2]), "=r"(r[3]) : "r"(addr));
}
__device__ __forceinline__ void cp16(uint32_t dst, const void* src) {
    asm volatile("cp.async.cg.shared.global [%0], [%1], 16;" :: "r"(dst), "l"(src));
}
#define CP_COMMIT() asm volatile("cp.async.commit_group;" ::: "memory")
#define CP_WAIT0()  asm volatile("cp.async.wait_group 0;" ::: "memory")
#define CP_WAIT1()  asm volatile("cp.async.wait_group 1;" ::: "memory")

// packed f32x2 (Blackwell): one instr = two independent fp32 FMAs
typedef unsigned long long u64p;
__device__ __forceinline__ u64p pk2(float lo, float hi) {
    u64p r; asm("mov.b64 %0, {%1, %2};" : "=l"(r) : "f"(lo), "f"(hi)); return r;
}
__device__ __forceinline__ void up2(u64p v, float& lo, float& hi) {
    asm("mov.b64 {%0, %1}, %2;" : "=f"(lo), "=f"(hi) : "l"(v));
}
__device__ __forceinline__ void ffma2(u64p& d, u64p a, u64p b) {
    asm("fma.rn.f32x2 %0, %1, %2, %0;" : "+l"(d) : "l"(a), "l"(b));
}

// Fill a 128x64-elem (16-bit) tile (XOR-swizzled 128B rows) via cp.async.
template <typename T>
__device__ __forceinline__ void fill_tile256(uint32_t dst, const T* src,
                                             int rstride, int tid) {
#pragma unroll
    for (int i = 0; i < 4; i++) {
        int idx = tid + i * 256;
        int r = idx >> 3, q = idx & 7;
        cp16(dst + r * 128 + ((q ^ (r & 7)) << 4), src + (size_t)r * rstride + q * 8);
    }
}

// ============================================================================
// pack kernels
// ============================================================================
__global__ void build_kt_tr(const float* __restrict__ conv_w) {
    __shared__ float sm[64][145];
    const int tid = threadIdx.x;
    const int c1 = blockIdx.x;
    const int cc0 = blockIdx.y * 64;
    const int w = c1 & 15, b = c1 >> 4;
    const float* src = conv_w + ((size_t)(w * 16 + b) * 256 + cc0) * 144;
    for (int idx = tid; idx < 64 * 144; idx += 256) {
        int c = idx / 144, l = idx - c * 144;
        sm[c][l] = src[c * 144 + l];
    }
    __syncthreads();
    for (int idx = tid; idx < 144 * 64; idx += 256) {
        int l = idx >> 6, c = idx & 63;
        __nv_bfloat16 h, lo;
        split2(sm[c][l], h, lo);
        size_t o = (size_t)(c1 * 144 + l) * 256 + cc0 + c;
        g_aph[o] = h;
        g_apl[o] = lo;
    }
}
__global__ void pack_bt(const float* __restrict__ W, __nv_bfloat16* __restrict__ oh,
                        __nv_bfloat16* __restrict__ ol, int N) {
    int idx = blockIdx.x * 256 + threadIdx.x;
    int k = idx & 255;
    int n = idx >> 8;
    __nv_bfloat16 h, l;
    split2(W[(size_t)k * N + n], h, l);
    oh[idx] = h;
    ol[idx] = l;
}
// x windows -> single fp16 plane [(b*16+w)*4+chunk][row=yy*18+xx][cin64]
__global__ void pack_x(const float* __restrict__ x) {
    extern __shared__ float sm[];        // [64][325]
    const int tid = threadIdx.x;
    const int wb = blockIdx.x;           // b*16 + w
    const int b = wb >> 4, w = wb & 15;
    const int h0 = (w >> 2) * WSZ;
    const int w0 = (w & 3) * WSZ;
    for (int chunk = 0; chunk < 4; chunk++) {
        const int c0 = chunk * 64;
        __syncthreads();
        for (int i = tid; i < 64 * 324; i += 256) {
            int ci = i / 324;
            int rem = i - ci * 324;
            int yy = rem / 18;
            int xx = rem - yy * 18;
            float v = 0.f;
            if ((unsigned)(yy - 1) < 16u && (unsigned)(xx - 1) < 16u)
                v = x[((size_t)(b * DIMC + c0 + ci) * IMG + h0 + yy - 1) * IMG + w0 + xx - 1];
            sm[ci * 325 + rem] = v;
        }
        __syncthreads();
        size_t obase = ((size_t)(wb * 4 + chunk)) * 324 * 64;
        for (int i = tid; i < 324 * 64; i += 256) {
            int row = i >> 6, ci = i & 63;
            g_xf[obase + i] = __float2half_rn(sm[ci * 325 + row]);
        }
    }
}

// ============================================================================
// GEMM: C[M,N] = A @ B^T + bias, K=256 (unchanged: bf16 3-pass).
// ============================================================================
#define G_AH 0
#define G_AL 16384
#define G_BH 32768
#define G_BL 49152
#define G_SMEM 65536

__global__ void __launch_bounds__(256, 2)
gemm_mma(const __nv_bfloat16* __restrict__ Ah, const __nv_bfloat16* __restrict__ Al,
         const __nv_bfloat16* __restrict__ Bh, const __nv_bfloat16* __restrict__ Bl,
         const float* __restrict__ bias, float* __restrict__ C, int N) {
    extern __shared__ char smem[];
    const uint32_t sb = smem_u32(smem);
    const int tid = threadIdx.x;
    const int lane = tid & 31;
    const int wid = tid >> 5;
    const int wm = wid & 3, wn = wid >> 2;
    const int m0 = blockIdx.y * 128, n0 = blockIdx.x * 128;
    const int lm = lane & 15, kh = lane >> 4;
    const int quad = lane >> 2, qt = lane & 3;
    const int l7 = lane & 7;
    const int kbit = (lane >> 3) & 1;
    const int nloc = ((lane >> 4) << 3) | l7;

    float acc[2][8][4] = {};

#pragma unroll 1
    for (int kc = 0; kc < 4; kc++) {
        const int k0 = kc * 64;
        fill_tile256(sb + G_AH, Ah + (size_t)m0 * 256 + k0, 256, tid);
        fill_tile256(sb + G_AL, Al + (size_t)m0 * 256 + k0, 256, tid);
        fill_tile256(sb + G_BH, Bh + (size_t)n0 * 256 + k0, 256, tid);
        fill_tile256(sb + G_BL, Bl + (size_t)n0 * 256 + k0, 256, tid);
        CP_COMMIT();
        CP_WAIT0();
        __syncthreads();

        const uint32_t AbH = sb + G_AH;
        const uint32_t AbL = sb + G_AL;
        const uint32_t BbH = sb + G_BH + (wn * 64 + nloc) * 128;
        const uint32_t BbL = sb + G_BL + (wn * 64 + nloc) * 128;
#pragma unroll
        for (int ks = 0; ks < 4; ks++) {
            uint32_t ah[2][4], al[2][4];
#pragma unroll
            for (int fm = 0; fm < 2; fm++) {
                int m = wm * 32 + fm * 16 + lm;
                uint32_t acol = (uint32_t)(((ks * 2 + kh) ^ (lm & 7)) << 4);
                ldsm4(ah[fm], AbH + m * 128 + acol);
                ldsm4(al[fm], AbL + m * 128 + acol);
            }
            const uint32_t bcol = (uint32_t)(((ks * 2 + kbit) ^ l7) << 4);
            uint32_t bh[4][4], bl[4][4];
#pragma unroll
            for (int p = 0; p < 4; p++) {
                ldsm4(bh[p], BbH + p * 2048 + bcol);
                ldsm4(bl[p], BbL + p * 2048 + bcol);
            }
#pragma unroll
            for (int p = 0; p < 4; p++)
#pragma unroll
                for (int fm = 0; fm < 2; fm++) {
                    mma16816(acc[fm][2 * p],     ah[fm], bh[p]);
                    mma16816(acc[fm][2 * p + 1], ah[fm], bh[p] + 2);
                }
#pragma unroll
            for (int p = 0; p < 4; p++)
#pragma unroll
                for (int fm = 0; fm < 2; fm++) {
                    mma16816(acc[fm][2 * p],     ah[fm], bl[p]);
                    mma16816(acc[fm][2 * p + 1], ah[fm], bl[p] + 2);
                }
#pragma unroll
            for (int p = 0; p < 4; p++)
#pragma unroll
                for (int fm = 0; fm < 2; fm++) {
                    mma16816(acc[fm][2 * p],     al[fm], bh[p]);
                    mma16816(acc[fm][2 * p + 1], al[fm], bh[p] + 2);
                }
        }
        __syncthreads();
    }

#pragma unroll
    for (int fm = 0; fm < 2; fm++) {
        int m = m0 + wm * 32 + fm * 16 + quad;
#pragma unroll
        for (int fn = 0; fn < 8; fn++) {
            int col = n0 + wn * 64 + fn * 8 + qt * 2;
            float b0 = bias[col], b1 = bias[col + 1];
            float* c = acc[fm][fn];
            *(float2*)&C[(size_t)m * N + col]       = make_float2(c[0] + b0, c[1] + b1);
            *(float2*)&C[(size_t)(m + 8) * N + col] = make_float2(c[2] + b0, c[3] + b1);
        }
    }
}

// ============================================================================
// attention — single pass, packed f32x2 FMA (unchanged)
// ============================================================================
__global__ void attn_kernel(const float* __restrict__ qkv) {
    const int c1 = blockIdx.x;
    const int h  = blockIdx.y;
    __shared__ float ks[TOK][HD];
    __shared__ float vs[TOK][HD];

    for (int idx = threadIdx.x; idx < TOK * HD; idx += blockDim.x) {
        int t = idx >> 5, e = idx & 31;
        size_t base = (size_t)(c1 * TOK + t) * 768 + h * HD + e;
        ks[t][e] = qkv[base + 256];
        vs[t][e] = qkv[base + 512];
    }
    __syncthreads();

    const int t = threadIdx.x;
    if (t < TOK) {
        const float scale = 0.17677669529663687f;
        u64p q2[16];
        {
            const float2* qsrc = (const float2*)(qkv + (size_t)(c1 * TOK + t) * 768 + h * HD);
#pragma unroll
            for (int i = 0; i < 16; i++) {
                float2 v = qsrc[i];
                q2[i] = pk2(v.x * scale, v.y * scale);
            }
        }

        u64p a2[16];
#pragma unroll
        for (int i = 0; i < 16; i++) a2[i] = pk2(0.f, 0.f);
        float denom = 0.f;

        for (int j = 0; j < TOK; j++) {
            const u64p* k2 = (const u64p*)ks[j];
            u64p s0 = pk2(0.f, 0.f), s1 = s0, s2 = s0, s3 = s0;
#pragma unroll
            for (int i = 0; i < 16; i += 4) {
                ffma2(s0, q2[i],     k2[i]);
                ffma2(s1, q2[i + 1], k2[i + 1]);
                ffma2(s2, q2[i + 2], k2[i + 2]);
                ffma2(s3, q2[i + 3], k2[i + 3]);
            }
            float x0, x1, y0, y1, z0, z1, w0, w1;
            up2(s0, x0, x1); up2(s1, y0, y1); up2(s2, z0, z1); up2(s3, w0, w1);
            float sc = ((x0 + x1) + (y0 + y1)) + ((z0 + z1) + (w0 + w1));
            float pexp = __expf(sc);
            denom += pexp;
            u64p pe2 = pk2(pexp, pexp);
            const u64p* v2 = (const u64p*)vs[j];
#pragma unroll
            for (int i = 0; i < 16; i++) ffma2(a2[i], pe2, v2[i]);
        }
        float inv = 1.f / denom;
        size_t ob = (size_t)(c1 * TOK + t) * DIMC + h * HD;
#pragma unroll
        for (int i = 0; i < 16; i++) {
            float v0, v1;
            up2(a2[i], v0, v1);
            __nv_bfloat16 h0, l0, h1, l1;
            split2(v0 * inv, h0, l0);
            split2(v1 * inv, h1, l1);
            g_aph[ob + i * 2]     = h0;
            g_aph[ob + i * 2 + 1] = h1;
            g_apl[ob + i * 2]     = l0;
            g_apl[ob + i * 2 + 1] = l1;
        }
    }
}

// ============================================================================
// SE gate (unchanged)
// ============================================================================
__global__ void se_kernel(const float* __restrict__ kp,
                          const float* __restrict__ se_w1, const float* __restrict__ se_b1,
                          const float* __restrict__ se_w2, const float* __restrict__ se_b2,
                          float* __restrict__ s_out) {
    const int i = blockIdx.x;
    const int w = blockIdx.y;
    __shared__ float pooled[DIMC];
    __shared__ float hsm[16];
    const int j = threadIdx.x;

    size_t base = (size_t)(i * TOK + w * 9) * DIMC + j;
    float p = 0.f;
#pragma unroll
    for (int tap = 0; tap < 9; tap++) p += kp[base + (size_t)tap * DIMC];
    pooled[j] = p * (1.f / 9.f);
    __syncthreads();

    if (j < 16) {
        float hv = se_b1[w * 16 + j];
        const float* w1 = se_w1 + (size_t)(w * 16 + j) * DIMC;
        for (int c = 0; c < DIMC; c++) hv += pooled[c] * w1[c];
        hsm[j] = fmaxf(hv, 0.f);
    }
    __syncthreads();

    float acc = se_b2[w * DIMC + j];
    const float* w2 = se_w2 + (size_t)(w * DIMC + j) * 16;
#pragma unroll
    for (int k = 0; k < 16; k++) acc += hsm[k] * w2[k];
    s_out[(size_t)(w * DIMC + i) * DIMC + j] = 1.f / (1.f + __expf(-acc));
}

// ============================================================================
// weight prep -> fp16 hi/lo planes  [((w*256+cout)*9+tap)*256 + cin]
// ============================================================================
__global__ void prep_w(const float* __restrict__ kp, const float* __restrict__ s) {
    int idx = blockIdx.x * 256 + threadIdx.x;
    int cin = idx & 255;
    int t2  = idx >> 8;
    int tap = t2 % 9;
    int t3  = t2 / 9;
    int cout = t3 & 255;
    int w    = t3 >> 8;
    float v = kp[(size_t)(cout * TOK + w * 9 + tap) * DIMC + cin]
            * s[(size_t)(w * DIMC + cout) * DIMC + cin];
    __half h = __float2half_rn(v);
    __half l = __float2half_rn(v - __half2float(h));
    g_wfh[idx] = h;
    g_wfl[idx] = l;
}

// ============================================================================
// grouped conv: warp-MMA fp16 implicit GEMM, 2-pass (A fp16, W hi/lo fp16).
// M=256, N=128, K=2304. 256 threads / 8 warps.
// xs DOUBLE-buffered (prefetch at tap 4); B triple-buffered.
// smem: XS0 41472 | XS1 41472 | 3 x B 32768 = 181248 B.
// ============================================================================
#define C_XSBUF 41472
#define C_BBASE 82944
#define C_BBUF  32768
#define C_SMEM  181248

__global__ void __launch_bounds__(256, 1)
conv_mma(float* __restrict__ y) {
    extern __shared__ char smem[];
    const uint32_t sb = smem_u32(smem);
    const int tid = threadIdx.x;
    const int lane = tid & 31;
    const int wid = tid >> 5;
    const int wm = wid & 3, wn = wid >> 2;
    const int nhalf = blockIdx.x;
    const int b = blockIdx.y;
    const int w = blockIdx.z;
    const int lm = lane & 15, kh = lane >> 4;
    const int quad = lane >> 2, qt = lane & 3;
    const int l7 = lane & 7;
    const int kbit = (lane >> 3) & 1;
    const int nloc = ((lane >> 4) << 3) | l7;
    const int wb = b * 16 + w;

    const __half* wfh = g_wfh + ((size_t)(w * 256 + nhalf * 128) * 9) * 256;
    const __half* wfl = g_wfl + ((size_t)(w * 256 + nhalf * 128) * 9) * 256;

    float acc[4][8][4] = {};

    auto xsfill = [&](int chunk) {
        const __half* src = g_xf + ((size_t)(wb * 4 + chunk)) * 324 * 64;
        const uint32_t xbuf = sb + (chunk & 1) * C_XSBUF;
        for (int i = tid; i < 2592; i += 256) {
            int r = i >> 3, q = i & 7;
            cp16(xbuf + r * 128 + ((q ^ (r & 7)) << 4), src + r * 64 + q * 8);
        }
    };
    auto bfill = [&](int kt) {
        int nc = kt / 9, nt = kt - nc * 9;
        uint32_t d = sb + C_BBASE + (kt % 3) * C_BBUF;
        fill_tile256(d,         wfh + (size_t)nt * 256 + nc * 64, 2304, tid);
        fill_tile256(d + 16384, wfl + (size_t)nt * 256 + nc * 64, 2304, tid);
    };

    // prologue: xs(0) [g], B(0) [g], B(1) [g]  -- one group each
    xsfill(0); CP_COMMIT();
    bfill(0);  CP_COMMIT();
    bfill(1);  CP_COMMIT();

#pragma unroll 1
    for (int kt = 0; kt < 36; kt++) {
        const int chunk = kt / 9;
        const int tap = kt - chunk * 9;

        // Wait: B(kt) committed 2 groups back -> WAIT1 suffices (most recent
        // pending = B(kt+1)). For the tail (no more commits) drain fully.
        if (kt >= 34) { CP_WAIT0(); } else { CP_WAIT1(); }
        __syncthreads();      // all warps done reading buf (kt+2)%3 at kt-1

        if (kt + 2 < 36) {
            bfill(kt + 2);
            if (tap == 4 && chunk < 3) xsfill(chunk + 1);   // prefetch next x tile
            CP_COMMIT();
        }

        const uint32_t Xb  = sb + (chunk & 1) * C_XSBUF;
        const uint32_t BbH = sb + C_BBASE + (kt % 3) * C_BBUF + (wn * 64 + nloc) * 128;
        const uint32_t BbL = BbH + 16384;

        const int ky = tap / 3, kx = tap - ky * 3;
        int arow[4];
#pragma unroll
        for (int fm = 0; fm < 4; fm++) {
            int p = wm * 64 + fm * 16 + lm;
            arow[fm] = ((p >> 4) + ky) * 18 + (p & 15) + kx;
        }

#pragma unroll
        for (int ks = 0; ks < 4; ks++) {
            uint32_t a[4][4];
#pragma unroll
            for (int fm = 0; fm < 4; fm++) {
                uint32_t acol = (uint32_t)(((ks * 2 + kh) ^ (arow[fm] & 7)) << 4);
                ldsm4(a[fm], Xb + arow[fm] * 128 + acol);
            }
            const uint32_t bcol = (uint32_t)(((ks * 2 + kbit) ^ l7) << 4);
            uint32_t bh[4][4], bl[4][4];
#pragma unroll
            for (int p = 0; p < 4; p++) {
                ldsm4(bh[p], BbH + p * 2048 + bcol);
                ldsm4(bl[p], BbL + p * 2048 + bcol);
            }
            // sweep 1: A * Wh  (32 independent accumulators)
#pragma unroll
            for (int p = 0; p < 4; p++)
#pragma unroll
                for (int fm = 0; fm < 4; fm++) {
                    mma16816h(acc[fm][2 * p],     a[fm], bh[p]);
                    mma16816h(acc[fm][2 * p + 1], a[fm], bh[p] + 2);
                }
            // sweep 2: A * Wl
#pragma unroll
            for (int p = 0; p < 4; p++)
#pragma unroll
                for (int fm = 0; fm < 4; fm++) {
                    mma16816h(acc[fm][2 * p],     a[fm], bl[p]);
                    mma16816h(acc[fm][2 * p + 1], a[fm], bl[p] + 2);
                }
        }
    }

    // ---- epilogue ----
    float* ybase = y + (size_t)((w * 16 + b) * 256) * 256 + nhalf * 128;
#pragma unroll
    for (int fm = 0; fm < 4; fm++) {
        int pos = wm * 64 + fm * 16 + quad;
#pragma unroll
        for (int fn = 0; fn < 8; fn++) {
            int col = wn * 64 + fn * 8 + qt * 2;
            float* c = acc[fm][fn];
            *(float2*)(ybase + (size_t)pos * 256 + col)       = make_float2(c[0], c[1]);
            *(float2*)(ybase + (size_t)(pos + 8) * 256 + col) = make_float2(c[2], c[3]);
        }
    }
}

// ============================================================================
// window reverse + channel LayerNorm + residual (unchanged)
// ============================================================================
__global__ void ln_kernel(const float* __restrict__ x, const float* __restrict__ y,
                          const float* __restrict__ ln_g, const float* __restrict__ ln_b,
                          float* __restrict__ out) {
    extern __shared__ float sm[];
    __shared__ float red[2][4][64];
    __shared__ float mu[64], rs[64];

    const int yy = blockIdx.x;
    const int b  = blockIdx.y;
    const int t  = threadIdx.x;
    const int hi = yy >> 4;
    const int py = yy & 15;

    for (int xx = 0; xx < 64; xx++) {
        int w = hi * 4 + (xx >> 4);
        int p = py * 16 + (xx & 15);
        sm[t * 65 + xx] = y[((size_t)((w * 16 + b) * 256 + p)) * DIMC + t];
    }
    __syncthreads();

    {
        int xx = t & 63, part = t >> 6;
        float s1 = 0.f, s2 = 0.f;
        for (int c = part * 64; c < part * 64 + 64; c++) {
            float v = sm[c * 65 + xx];
            s1 += v; s2 += v * v;
        }
        red[0][part][xx] = s1;
        red[1][part][xx] = s2;
    }
    __syncthreads();
    if (t < 64) {
        float S = 0.f, S2 = 0.f;
#pragma unroll
        for (int p2 = 0; p2 < 4; p2++) { S += red[0][p2][t]; S2 += red[1][p2][t]; }
        float m = S * (1.f / 256.f);
        float var = S2 * (1.f / 256.f) - m * m;
        mu[t] = m;
        rs[t] = rsqrtf(var + 1e-5f);
    }
    __syncthreads();

    for (int idx = t; idx < 256 * 64; idx += 256) {
        int c  = idx >> 6;
        int xi = idx & 63;
        float v = (sm[c * 65 + xi] - mu[xi]) * rs[xi] * ln_g[c] + ln_b[c];
        size_t oidx = ((size_t)(b * DIMC + c) * IMG + yy) * IMG + xi;
        out[oidx] = x[oidx] + v;
    }
}

// ============================================================================
// launch
// ============================================================================
extern "C" void kernel_launch(void* const* d_in, const int* in_sizes, int n_in,
                              void* d_out, int out_size) {
    const float* x      = (const float*)d_in[0];
    const float* conv_w = (const float*)d_in[1];
    const float* wqkv   = (const float*)d_in[2];
    const float* bqkv   = (const float*)d_in[3];
    const float* wout   = (const float*)d_in[4];
    const float* bout   = (const float*)d_in[5];
    const float* se_w1  = (const float*)d_in[6];
    const float* se_b1  = (const float*)d_in[7];
    const float* se_w2  = (const float*)d_in[8];
    const float* se_b2  = (const float*)d_in[9];
    const float* ln_g   = (const float*)d_in[10];
    const float* ln_b   = (const float*)d_in[11];
    float* out = (float*)d_out;

    float *qkvb, *kpb, *sbuf, *yb;
    __nv_bfloat16 *aph, *apl, *bqh, *bql, *bwh, *bwl;
    cudaGetSymbolAddress((void**)&qkvb, g_qkv);
    cudaGetSymbolAddress((void**)&kpb,  g_kp);
    cudaGetSymbolAddress((void**)&sbuf, g_s);
    cudaGetSymbolAddress((void**)&yb,   g_y);
    cudaGetSymbolAddress((void**)&aph,  g_aph);
    cudaGetSymbolAddress((void**)&apl,  g_apl);
    cudaGetSymbolAddress((void**)&bqh,  g_bqh);
    cudaGetSymbolAddress((void**)&bql,  g_bql);
    cudaGetSymbolAddress((void**)&bwh,  g_bwh);
    cudaGetSymbolAddress((void**)&bwl,  g_bwl);

    cudaFuncSetAttribute(conv_mma, cudaFuncAttributeMaxDynamicSharedMemorySize, C_SMEM);
    cudaFuncSetAttribute(gemm_mma, cudaFuncAttributeMaxDynamicSharedMemorySize, G_SMEM);
    cudaFuncSetAttribute(pack_x, cudaFuncAttributeMaxDynamicSharedMemorySize,
                         64 * 325 * (int)sizeof(float));
    cudaFuncSetAttribute(ln_kernel, cudaFuncAttributeMaxDynamicSharedMemorySize,
                         256 * 65 * (int)sizeof(float));

    // pack weights
    pack_bt<<<3 * DIMC, 256>>>(wqkv, bqh, bql, 3 * DIMC);
    pack_bt<<<DIMC, 256>>>(wout, bwh, bwl, DIMC);

    // kt planes from conv_w (tiled transpose)
    build_kt_tr<<<dim3(256, 4), 256>>>(conv_w);

    // qkv = kt @ wqkv + bqkv
    gemm_mma<<<dim3(6, MROWS / 128), 256, G_SMEM>>>(aph, apl, bqh, bql, bqkv, qkvb, 3 * DIMC);

    // x windows pack (independent; only needed before conv)
    pack_x<<<BATCH * WN, 256, 64 * 325 * sizeof(float)>>>(x);

    // attention (writes A planes for wout gemm)
    attn_kernel<<<dim3(DIMC, HEADS), 160>>>(qkvb);

    // kp = o @ wout + bout
    gemm_mma<<<dim3(2, MROWS / 128), 256, G_SMEM>>>(aph, apl, bwh, bwl, bout, kpb, DIMC);

    // SE gate
    se_kernel<<<dim3(DIMC, WN), 256>>>(kpb, se_w1, se_b1, se_w2, se_b2, sbuf);

    // gated weight fp16 hi/lo planes
    prep_w<<<WN * DIMC * 9, 256>>>(kpb, sbuf);

    // grouped conv on tensor cores (fp16 2-pass, xs double-buffered)
    conv_mma<<<dim3(2, BATCH, WN), 256, C_SMEM>>>(yb);

    // window reverse + LN + residual
    ln_kernel<<<dim3(IMG, BATCH), 256, 256 * 65 * sizeof(float)>>>(x, yb, ln_g, ln_b, out);
}

// round 16
// speedup vs baseline: 1.1642x; 1.0107x over previous
#include <cuda_runtime.h>
#include <cuda_bf16.h>
#include <cuda_fp16.h>
#include <stdint.h>
#include <math.h>

// ---------------- problem constants ----------------
#define DIMC   256
#define HEADS  8
#define HD     32
#define WSZ    16
#define WN     16
#define KS     3
#define BATCH  16
#define IMG    64
#define TOK    144
#define MROWS  36864               // DIMC*TOK

// ---------------- scratch ----------------
__device__ float          g_qkv[MROWS * 3 * DIMC];
__device__ float          g_kp [MROWS * DIMC];
__device__ float          g_s  [WN * DIMC * DIMC];
__device__ float          g_y  [WN * BATCH * 256 * DIMC];   // (w,b,pos,cout)
__device__ __nv_bfloat16  g_aph[MROWS * DIMC];              // A hi plane (kt, then attn-o)
__device__ __nv_bfloat16  g_apl[MROWS * DIMC];              // A lo plane
__device__ __nv_bfloat16  g_bqh[3 * DIMC * DIMC];           // wqkv^T hi [n][k]
__device__ __nv_bfloat16  g_bql[3 * DIMC * DIMC];
__device__ __nv_bfloat16  g_bwh[DIMC * DIMC];               // wout^T hi [n][k]
__device__ __nv_bfloat16  g_bwl[DIMC * DIMC];
__device__ __half         g_wfh[WN * DIMC * 9 * DIMC];      // gated conv W fp16 hi [w][cout][tap][cin]
__device__ __half         g_wfl[WN * DIMC * 9 * DIMC];      // fp16 lo
__device__ __half         g_xf [BATCH * WN * 4 * 324 * 64]; // x windows fp16 [(b*16+w)*4+chunk][row][cin64]

// ============================================================================
// helpers
// ============================================================================
__device__ __forceinline__ uint32_t smem_u32(const void* p) {
    uint32_t a;
    asm("{ .reg .u64 t; cvta.to.shared.u64 t, %1; cvt.u32.u64 %0, t; }" : "=r"(a) : "l"(p));
    return a;
}
__device__ __forceinline__ void split2(float v, __nv_bfloat16& h, __nv_bfloat16& l) {
    h = __float2bfloat16(v);
    l = __float2bfloat16(v - __bfloat162float(h));
}
__device__ __forceinline__ void mma16816(float* d, const uint32_t* a, const uint32_t* b) {
    asm volatile("mma.sync.aligned.m16n8k16.row.col.f32.bf16.bf16.f32 "
        "{%0,%1,%2,%3}, {%4,%5,%6,%7}, {%8,%9}, {%0,%1,%2,%3};"
        : "+f"(d[0]), "+f"(d[1]), "+f"(d[2]), "+f"(d[3])
        : "r"(a[0]), "r"(a[1]), "r"(a[2]), "r"(a[3]), "r"(b[0]), "r"(b[1]));
}
__device__ __forceinline__ void mma16816h(float* d, const uint32_t* a, const uint32_t* b) {
    asm volatile("mma.sync.aligned.m16n8k16.row.col.f32.f16.f16.f32 "
        "{%0,%1,%2,%3}, {%4,%5,%6,%7}, {%8,%9}, {%0,%1,%2,%3};"
        : "+f"(d[0]), "+f"(d[1]), "+f"(d[2]), "+f"(d[3])
        : "r"(a[0]), "r"(a[1]), "r"(a[2]), "r"(a[3]), "r"(b[0]), "r"(b[1]));
}
__device__ __forceinline__ void ldsm4(uint32_t* r, uint32_t addr) {
    asm volatile("ldmatrix.sync.aligned.m8n8.x4.shared.b16 {%0,%1,%2,%3}, [%4];"
        : "=r"(r[0]), "=r"(r[1]), "=r"(r[2]), "=r"(r[3]) : "r"(addr));
}
__device__ __forceinline__ void cp16(uint32_t dst, const void* src) {
    asm volatile("cp.async.cg.shared.global [%0], [%1], 16;" :: "r"(dst), "l"(src));
}
#define CP_COMMIT() asm volatile("cp.async.commit_group;" ::: "memory")
#define CP_WAIT0()  asm volatile("cp.async.wait_group 0;" ::: "memory")
#define CP_WAIT1()  asm volatile("cp.async.wait_group 1;" ::: "memory")

// packed f32x2 (Blackwell): one instr = two independent fp32 FMAs
typedef unsigned long long u64p;
__device__ __forceinline__ u64p pk2(float lo, float hi) {
    u64p r; asm("mov.b64 %0, {%1, %2};" : "=l"(r) : "f"(lo), "f"(hi)); return r;
}
__device__ __forceinline__ void up2(u64p v, float& lo, float& hi) {
    asm("mov.b64 {%0, %1}, %2;" : "=f"(lo), "=f"(hi) : "l"(v));
}
__device__ __forceinline__ void ffma2(u64p& d, u64p a, u64p b) {
    asm("fma.rn.f32x2 %0, %1, %2, %0;" : "+l"(d) : "l"(a), "l"(b));
}

// Fill a 128x64-elem (16-bit) tile (XOR-swizzled 128B rows) via cp.async.
template <typename T>
__device__ __forceinline__ void fill_tile256(uint32_t dst, const T* src,
                                             int rstride, int tid) {
#pragma unroll
    for (int i = 0; i < 4; i++) {
        int idx = tid + i * 256;
        int r = idx >> 3, q = idx & 7;
        cp16(dst + r * 128 + ((q ^ (r & 7)) << 4), src + (size_t)r * rstride + q * 8);
    }
}

// ============================================================================
// pack kernels
// ============================================================================
__global__ void build_kt_tr(const float* __restrict__ conv_w) {
    __shared__ float sm[64][145];
    const int tid = threadIdx.x;
    const int c1 = blockIdx.x;
    const int cc0 = blockIdx.y * 64;
    const int w = c1 & 15, b = c1 >> 4;
    const float* src = conv_w + ((size_t)(w * 16 + b) * 256 + cc0) * 144;
    for (int idx = tid; idx < 64 * 144; idx += 256) {
        int c = idx / 144, l = idx - c * 144;
        sm[c][l] = src[c * 144 + l];
    }
    __syncthreads();
    for (int idx = tid; idx < 144 * 64; idx += 256) {
        int l = idx >> 6, c = idx & 63;
        __nv_bfloat16 h, lo;
        split2(sm[c][l], h, lo);
        size_t o = (size_t)(c1 * 144 + l) * 256 + cc0 + c;
        g_aph[o] = h;
        g_apl[o] = lo;
    }
}
__global__ void pack_bt(const float* __restrict__ W, __nv_bfloat16* __restrict__ oh,
                        __nv_bfloat16* __restrict__ ol, int N) {
    int idx = blockIdx.x * 256 + threadIdx.x;
    int k = idx & 255;
    int n = idx >> 8;
    __nv_bfloat16 h, l;
    split2(W[(size_t)k * N + n], h, l);
    oh[idx] = h;
    ol[idx] = l;
}
// x windows -> single fp16 plane [(b*16+w)*4+chunk][row=yy*18+xx][cin64]
__global__ void pack_x(const float* __restrict__ x) {
    extern __shared__ float sm[];        // [64][325]
    const int tid = threadIdx.x;
    const int wb = blockIdx.x;           // b*16 + w
    const int b = wb >> 4, w = wb & 15;
    const int h0 = (w >> 2) * WSZ;
    const int w0 = (w & 3) * WSZ;
    for (int chunk = 0; chunk < 4; chunk++) {
        const int c0 = chunk * 64;
        __syncthreads();
        for (int i = tid; i < 64 * 324; i += 256) {
            int ci = i / 324;
            int rem = i - ci * 324;
            int yy = rem / 18;
            int xx = rem - yy * 18;
            float v = 0.f;
            if ((unsigned)(yy - 1) < 16u && (unsigned)(xx - 1) < 16u)
                v = x[((size_t)(b * DIMC + c0 + ci) * IMG + h0 + yy - 1) * IMG + w0 + xx - 1];
            sm[ci * 325 + rem] = v;
        }
        __syncthreads();
        size_t obase = ((size_t)(wb * 4 + chunk)) * 324 * 64;
        for (int i = tid; i < 324 * 64; i += 256) {
            int row = i >> 6, ci = i & 63;
            g_xf[obase + i] = __float2half_rn(sm[ci * 325 + row]);
        }
    }
}

// ============================================================================
// GEMM: C[M,N] = A @ B^T + bias, K=256 (unchanged: bf16 3-pass).
// ============================================================================
#define G_AH 0
#define G_AL 16384
#define G_BH 32768
#define G_BL 49152
#define G_SMEM 65536

__global__ void __launch_bounds__(256, 2)
gemm_mma(const __nv_bfloat16* __restrict__ Ah, const __nv_bfloat16* __restrict__ Al,
         const __nv_bfloat16* __restrict__ Bh, const __nv_bfloat16* __restrict__ Bl,
         const float* __restrict__ bias, float* __restrict__ C, int N) {
    extern __shared__ char smem[];
    const uint32_t sb = smem_u32(smem);
    const int tid = threadIdx.x;
    const int lane = tid & 31;
    const int wid = tid >> 5;
    const int wm = wid & 3, wn = wid >> 2;
    const int m0 = blockIdx.y * 128, n0 = blockIdx.x * 128;
    const int lm = lane & 15, kh = lane >> 4;
    const int quad = lane >> 2, qt = lane & 3;
    const int l7 = lane & 7;
    const int kbit = (lane >> 3) & 1;
    const int nloc = ((lane >> 4) << 3) | l7;

    float acc[2][8][4] = {};

#pragma unroll 1
    for (int kc = 0; kc < 4; kc++) {
        const int k0 = kc * 64;
        fill_tile256(sb + G_AH, Ah + (size_t)m0 * 256 + k0, 256, tid);
        fill_tile256(sb + G_AL, Al + (size_t)m0 * 256 + k0, 256, tid);
        fill_tile256(sb + G_BH, Bh + (size_t)n0 * 256 + k0, 256, tid);
        fill_tile256(sb + G_BL, Bl + (size_t)n0 * 256 + k0, 256, tid);
        CP_COMMIT();
        CP_WAIT0();
        __syncthreads();

        const uint32_t AbH = sb + G_AH;
        const uint32_t AbL = sb + G_AL;
        const uint32_t BbH = sb + G_BH + (wn * 64 + nloc) * 128;
        const uint32_t BbL = sb + G_BL + (wn * 64 + nloc) * 128;
#pragma unroll
        for (int ks = 0; ks < 4; ks++) {
            uint32_t ah[2][4], al[2][4];
#pragma unroll
            for (int fm = 0; fm < 2; fm++) {
                int m = wm * 32 + fm * 16 + lm;
                uint32_t acol = (uint32_t)(((ks * 2 + kh) ^ (lm & 7)) << 4);
                ldsm4(ah[fm], AbH + m * 128 + acol);
                ldsm4(al[fm], AbL + m * 128 + acol);
            }
            const uint32_t bcol = (uint32_t)(((ks * 2 + kbit) ^ l7) << 4);
            uint32_t bh[4][4], bl[4][4];
#pragma unroll
            for (int p = 0; p < 4; p++) {
                ldsm4(bh[p], BbH + p * 2048 + bcol);
                ldsm4(bl[p], BbL + p * 2048 + bcol);
            }
#pragma unroll
            for (int p = 0; p < 4; p++)
#pragma unroll
                for (int fm = 0; fm < 2; fm++) {
                    mma16816(acc[fm][2 * p],     ah[fm], bh[p]);
                    mma16816(acc[fm][2 * p + 1], ah[fm], bh[p] + 2);
                }
#pragma unroll
            for (int p = 0; p < 4; p++)
#pragma unroll
                for (int fm = 0; fm < 2; fm++) {
                    mma16816(acc[fm][2 * p],     ah[fm], bl[p]);
                    mma16816(acc[fm][2 * p + 1], ah[fm], bl[p] + 2);
                }
#pragma unroll
            for (int p = 0; p < 4; p++)
#pragma unroll
                for (int fm = 0; fm < 2; fm++) {
                    mma16816(acc[fm][2 * p],     al[fm], bh[p]);
                    mma16816(acc[fm][2 * p + 1], al[fm], bh[p] + 2);
                }
        }
        __syncthreads();
    }

#pragma unroll
    for (int fm = 0; fm < 2; fm++) {
        int m = m0 + wm * 32 + fm * 16 + quad;
#pragma unroll
        for (int fn = 0; fn < 8; fn++) {
            int col = n0 + wn * 64 + fn * 8 + qt * 2;
            float b0 = bias[col], b1 = bias[col + 1];
            float* c = acc[fm][fn];
            *(float2*)&C[(size_t)m * N + col]       = make_float2(c[0] + b0, c[1] + b1);
            *(float2*)&C[(size_t)(m + 8) * N + col] = make_float2(c[2] + b0, c[3] + b1);
        }
    }
}

// ============================================================================
// attention — single pass, packed f32x2 FMA (unchanged)
// ============================================================================
__global__ void attn_kernel(const float* __restrict__ qkv) {
    const int c1 = blockIdx.x;
    const int h  = blockIdx.y;
    __shared__ float ks[TOK][HD];
    __shared__ float vs[TOK][HD];

    for (int idx = threadIdx.x; idx < TOK * HD; idx += blockDim.x) {
        int t = idx >> 5, e = idx & 31;
        size_t base = (size_t)(c1 * TOK + t) * 768 + h * HD + e;
        ks[t][e] = qkv[base + 256];
        vs[t][e] = qkv[base + 512];
    }
    __syncthreads();

    const int t = threadIdx.x;
    if (t < TOK) {
        const float scale = 0.17677669529663687f;
        u64p q2[16];
        {
            const float2* qsrc = (const float2*)(qkv + (size_t)(c1 * TOK + t) * 768 + h * HD);
#pragma unroll
            for (int i = 0; i < 16; i++) {
                float2 v = qsrc[i];
                q2[i] = pk2(v.x * scale, v.y * scale);
            }
        }

        u64p a2[16];
#pragma unroll
        for (int i = 0; i < 16; i++) a2[i] = pk2(0.f, 0.f);
        float denom = 0.f;

        for (int j = 0; j < TOK; j++) {
            const u64p* k2 = (const u64p*)ks[j];
            u64p s0 = pk2(0.f, 0.f), s1 = s0, s2 = s0, s3 = s0;
#pragma unroll
            for (int i = 0; i < 16; i += 4) {
                ffma2(s0, q2[i],     k2[i]);
                ffma2(s1, q2[i + 1], k2[i + 1]);
                ffma2(s2, q2[i + 2], k2[i + 2]);
                ffma2(s3, q2[i + 3], k2[i + 3]);
            }
            float x0, x1, y0, y1, z0, z1, w0, w1;
            up2(s0, x0, x1); up2(s1, y0, y1); up2(s2, z0, z1); up2(s3, w0, w1);
            float sc = ((x0 + x1) + (y0 + y1)) + ((z0 + z1) + (w0 + w1));
            float pexp = __expf(sc);
            denom += pexp;
            u64p pe2 = pk2(pexp, pexp);
            const u64p* v2 = (const u64p*)vs[j];
#pragma unroll
            for (int i = 0; i < 16; i++) ffma2(a2[i], pe2, v2[i]);
        }
        float inv = 1.f / denom;
        size_t ob = (size_t)(c1 * TOK + t) * DIMC + h * HD;
#pragma unroll
        for (int i = 0; i < 16; i++) {
            float v0, v1;
            up2(a2[i], v0, v1);
            __nv_bfloat16 h0, l0, h1, l1;
            split2(v0 * inv, h0, l0);
            split2(v1 * inv, h1, l1);
            g_aph[ob + i * 2]     = h0;
            g_aph[ob + i * 2 + 1] = h1;
            g_apl[ob + i * 2]     = l0;
            g_apl[ob + i * 2 + 1] = l1;
        }
    }
}

// ============================================================================
// SE gate (unchanged)
// ============================================================================
__global__ void se_kernel(const float* __restrict__ kp,
                          const float* __restrict__ se_w1, const float* __restrict__ se_b1,
                          const float* __restrict__ se_w2, const float* __restrict__ se_b2,
                          float* __restrict__ s_out) {
    const int i = blockIdx.x;
    const int w = blockIdx.y;
    __shared__ float pooled[DIMC];
    __shared__ float hsm[16];
    const int j = threadIdx.x;

    size_t base = (size_t)(i * TOK + w * 9) * DIMC + j;
    float p = 0.f;
#pragma unroll
    for (int tap = 0; tap < 9; tap++) p += kp[base + (size_t)tap * DIMC];
    pooled[j] = p * (1.f / 9.f);
    __syncthreads();

    if (j < 16) {
        float hv = se_b1[w * 16 + j];
        const float* w1 = se_w1 + (size_t)(w * 16 + j) * DIMC;
        for (int c = 0; c < DIMC; c++) hv += pooled[c] * w1[c];
        hsm[j] = fmaxf(hv, 0.f);
    }
    __syncthreads();

    float acc = se_b2[w * DIMC + j];
    const float* w2 = se_w2 + (size_t)(w * DIMC + j) * 16;
#pragma unroll
    for (int k = 0; k < 16; k++) acc += hsm[k] * w2[k];
    s_out[(size_t)(w * DIMC + i) * DIMC + j] = 1.f / (1.f + __expf(-acc));
}

// ============================================================================
// weight prep -> fp16 hi/lo planes  [((w*256+cout)*9+tap)*256 + cin]
// ============================================================================
__global__ void prep_w(const float* __restrict__ kp, const float* __restrict__ s) {
    int idx = blockIdx.x * 256 + threadIdx.x;
    int cin = idx & 255;
    int t2  = idx >> 8;
    int tap = t2 % 9;
    int t3  = t2 / 9;
    int cout = t3 & 255;
    int w    = t3 >> 8;
    float v = kp[(size_t)(cout * TOK + w * 9 + tap) * DIMC + cin]
            * s[(size_t)(w * DIMC + cout) * DIMC + cin];
    __half h = __float2half_rn(v);
    __half l = __float2half_rn(v - __half2float(h));
    g_wfh[idx] = h;
    g_wfl[idx] = l;
}

// ============================================================================
// grouped conv: warp-MMA fp16 implicit GEMM, 2-pass (A fp16, W hi/lo fp16).
// M=256, N=128, K=2304. 256 threads / 8 warps.
// TWO TAPS PER BARRIER ROUND (18 rounds): B = 2 sets x 2 tiles (32 KB each),
// xs double-buffered with chunk prefetch at rounds 3/8/12.
// smem: XS0 41472 | XS1 41472 | B 4 x 32768 = 214016 B.
// ============================================================================
#define C_XSBUF 41472
#define C_BBASE 82944
#define C_SMEM  214016

__global__ void __launch_bounds__(256, 1)
conv_mma(float* __restrict__ y) {
    extern __shared__ char smem[];
    const uint32_t sb = smem_u32(smem);
    const int tid = threadIdx.x;
    const int lane = tid & 31;
    const int wid = tid >> 5;
    const int wm = wid & 3, wn = wid >> 2;
    const int nhalf = blockIdx.x;
    const int b = blockIdx.y;
    const int w = blockIdx.z;
    const int lm = lane & 15, kh = lane >> 4;
    const int quad = lane >> 2, qt = lane & 3;
    const int l7 = lane & 7;
    const int kbit = (lane >> 3) & 1;
    const int nloc = ((lane >> 4) << 3) | l7;
    const int wb = b * 16 + w;

    const __half* wfh = g_wfh + ((size_t)(w * 256 + nhalf * 128) * 9) * 256;
    const __half* wfl = g_wfl + ((size_t)(w * 256 + nhalf * 128) * 9) * 256;

    float acc[4][8][4] = {};

    auto xsfill = [&](int chunk) {
        const __half* src = g_xf + ((size_t)(wb * 4 + chunk)) * 324 * 64;
        const uint32_t xbuf = sb + (chunk & 1) * C_XSBUF;
        for (int i = tid; i < 2592; i += 256) {
            int r = i >> 3, q = i & 7;
            cp16(xbuf + r * 128 + ((q ^ (r & 7)) << 4), src + r * 64 + q * 8);
        }
    };
    // fill set t%2 with taps 2t, 2t+1 (hi+lo planes each)
    auto bfill2 = [&](int t) {
#pragma unroll
        for (int j = 0; j < 2; j++) {
            int kt = 2 * t + j;
            int nc = kt / 9, nt = kt - nc * 9;
            uint32_t d = sb + C_BBASE + (t & 1) * 65536 + j * 32768;
            fill_tile256(d,         wfh + (size_t)nt * 256 + nc * 64, 2304, tid);
            fill_tile256(d + 16384, wfl + (size_t)nt * 256 + nc * 64, 2304, tid);
        }
    };

    // prologue: xs(0), B set 0 (taps 0,1)
    xsfill(0);  CP_COMMIT();
    bfill2(0);  CP_COMMIT();

#pragma unroll 1
    for (int t = 0; t < 18; t++) {
        CP_WAIT0();          // set t and any xs chunk committed earlier are ready
        __syncthreads();     // all warps done reading set (t+1)%2 from round t-1

        if (t == 3)  { xsfill(1); CP_COMMIT(); }
        if (t == 8)  { xsfill(2); CP_COMMIT(); }
        if (t == 12) { xsfill(3); CP_COMMIT(); }
        if (t < 17)  { bfill2(t + 1); CP_COMMIT(); }

#pragma unroll
        for (int j = 0; j < 2; j++) {
            const int kt = 2 * t + j;
            const int chunk = kt / 9;
            const uint32_t Xb  = sb + (chunk & 1) * C_XSBUF;
            const uint32_t BbH = sb + C_BBASE + (t & 1) * 65536 + j * 32768
                               + (wn * 64 + nloc) * 128;
            const uint32_t BbL = BbH + 16384;
            const int tap = kt - chunk * 9;
            const int ky = tap / 3, kx = tap - ky * 3;
            int arow[4];
#pragma unroll
            for (int fm = 0; fm < 4; fm++) {
                int p = wm * 64 + fm * 16 + lm;
                arow[fm] = ((p >> 4) + ky) * 18 + (p & 15) + kx;
            }

#pragma unroll
            for (int ksl = 0; ksl < 4; ksl++) {
                uint32_t a[4][4];
#pragma unroll
                for (int fm = 0; fm < 4; fm++) {
                    uint32_t acol = (uint32_t)(((ksl * 2 + kh) ^ (arow[fm] & 7)) << 4);
                    ldsm4(a[fm], Xb + arow[fm] * 128 + acol);
                }
                const uint32_t bcol = (uint32_t)(((ksl * 2 + kbit) ^ l7) << 4);
                uint32_t bh[4][4], bl[4][4];
#pragma unroll
                for (int p = 0; p < 4; p++) {
                    ldsm4(bh[p], BbH + p * 2048 + bcol);
                    ldsm4(bl[p], BbL + p * 2048 + bcol);
                }
                // sweep 1: A * Wh  (32 independent accumulators)
#pragma unroll
                for (int p = 0; p < 4; p++)
#pragma unroll
                    for (int fm = 0; fm < 4; fm++) {
                        mma16816h(acc[fm][2 * p],     a[fm], bh[p]);
                        mma16816h(acc[fm][2 * p + 1], a[fm], bh[p] + 2);
                    }
                // sweep 2: A * Wl
#pragma unroll
                for (int p = 0; p < 4; p++)
#pragma unroll
                    for (int fm = 0; fm < 4; fm++) {
                        mma16816h(acc[fm][2 * p],     a[fm], bl[p]);
                        mma16816h(acc[fm][2 * p + 1], a[fm], bl[p] + 2);
                    }
            }
        }
    }

    // ---- epilogue ----
    float* ybase = y + (size_t)((w * 16 + b) * 256) * 256 + nhalf * 128;
#pragma unroll
    for (int fm = 0; fm < 4; fm++) {
        int pos = wm * 64 + fm * 16 + quad;
#pragma unroll
        for (int fn = 0; fn < 8; fn++) {
            int col = wn * 64 + fn * 8 + qt * 2;
            float* c = acc[fm][fn];
            *(float2*)(ybase + (size_t)pos * 256 + col)       = make_float2(c[0], c[1]);
            *(float2*)(ybase + (size_t)(pos + 8) * 256 + col) = make_float2(c[2], c[3]);
        }
    }
}

// ============================================================================
// window reverse + channel LayerNorm + residual (unchanged)
// ============================================================================
__global__ void ln_kernel(const float* __restrict__ x, const float* __restrict__ y,
                          const float* __restrict__ ln_g, const float* __restrict__ ln_b,
                          float* __restrict__ out) {
    extern __shared__ float sm[];
    __shared__ float red[2][4][64];
    __shared__ float mu[64], rs[64];

    const int yy = blockIdx.x;
    const int b  = blockIdx.y;
    const int t  = threadIdx.x;
    const int hi = yy >> 4;
    const int py = yy & 15;

    for (int xx = 0; xx < 64; xx++) {
        int w = hi * 4 + (xx >> 4);
        int p = py * 16 + (xx & 15);
        sm[t * 65 + xx] = y[((size_t)((w * 16 + b) * 256 + p)) * DIMC + t];
    }
    __syncthreads();

    {
        int xx = t & 63, part = t >> 6;
        float s1 = 0.f, s2 = 0.f;
        for (int c = part * 64; c < part * 64 + 64; c++) {
            float v = sm[c * 65 + xx];
            s1 += v; s2 += v * v;
        }
        red[0][part][xx] = s1;
        red[1][part][xx] = s2;
    }
    __syncthreads();
    if (t < 64) {
        float S = 0.f, S2 = 0.f;
#pragma unroll
        for (int p2 = 0; p2 < 4; p2++) { S += red[0][p2][t]; S2 += red[1][p2][t]; }
        float m = S * (1.f / 256.f);
        float var = S2 * (1.f / 256.f) - m * m;
        mu[t] = m;
        rs[t] = rsqrtf(var + 1e-5f);
    }
    __syncthreads();

    for (int idx = t; idx < 256 * 64; idx += 256) {
        int c  = idx >> 6;
        int xi = idx & 63;
        float v = (sm[c * 65 + xi] - mu[xi]) * rs[xi] * ln_g[c] + ln_b[c];
        size_t oidx = ((size_t)(b * DIMC + c) * IMG + yy) * IMG + xi;
        out[oidx] = x[oidx] + v;
    }
}

// ============================================================================
// launch
// ============================================================================
extern "C" void kernel_launch(void* const* d_in, const int* in_sizes, int n_in,
                              void* d_out, int out_size) {
    const float* x      = (const float*)d_in[0];
    const float* conv_w = (const float*)d_in[1];
    const float* wqkv   = (const float*)d_in[2];
    const float* bqkv   = (const float*)d_in[3];
    const float* wout   = (const float*)d_in[4];
    const float* bout   = (const float*)d_in[5];
    const float* se_w1  = (const float*)d_in[6];
    const float* se_b1  = (const float*)d_in[7];
    const float* se_w2  = (const float*)d_in[8];
    const float* se_b2  = (const float*)d_in[9];
    const float* ln_g   = (const float*)d_in[10];
    const float* ln_b   = (const float*)d_in[11];
    float* out = (float*)d_out;

    float *qkvb, *kpb, *sbuf, *yb;
    __nv_bfloat16 *aph, *apl, *bqh, *bql, *bwh, *bwl;
    cudaGetSymbolAddress((void**)&qkvb, g_qkv);
    cudaGetSymbolAddress((void**)&kpb,  g_kp);
    cudaGetSymbolAddress((void**)&sbuf, g_s);
    cudaGetSymbolAddress((void**)&yb,   g_y);
    cudaGetSymbolAddress((void**)&aph,  g_aph);
    cudaGetSymbolAddress((void**)&apl,  g_apl);
    cudaGetSymbolAddress((void**)&bqh,  g_bqh);
    cudaGetSymbolAddress((void**)&bql,  g_bql);
    cudaGetSymbolAddress((void**)&bwh,  g_bwh);
    cudaGetSymbolAddress((void**)&bwl,  g_bwl);

    cudaFuncSetAttribute(conv_mma, cudaFuncAttributeMaxDynamicSharedMemorySize, C_SMEM);
    cudaFuncSetAttribute(gemm_mma, cudaFuncAttributeMaxDynamicSharedMemorySize, G_SMEM);
    cudaFuncSetAttribute(pack_x, cudaFuncAttributeMaxDynamicSharedMemorySize,
                         64 * 325 * (int)sizeof(float));
    cudaFuncSetAttribute(ln_kernel, cudaFuncAttributeMaxDynamicSharedMemorySize,
                         256 * 65 * (int)sizeof(float));

    // pack weights
    pack_bt<<<3 * DIMC, 256>>>(wqkv, bqh, bql, 3 * DIMC);
    pack_bt<<<DIMC, 256>>>(wout, bwh, bwl, DIMC);

    // kt planes from conv_w (tiled transpose)
    build_kt_tr<<<dim3(256, 4), 256>>>(conv_w);

    // qkv = kt @ wqkv + bqkv
    gemm_mma<<<dim3(6, MROWS / 128), 256, G_SMEM>>>(aph, apl, bqh, bql, bqkv, qkvb, 3 * DIMC);

    // x windows pack (independent; only needed before conv)
    pack_x<<<BATCH * WN, 256, 64 * 325 * sizeof(float)>>>(x);

    // attention (writes A planes for wout gemm)
    attn_kernel<<<dim3(DIMC, HEADS), 160>>>(qkvb);

    // kp = o @ wout + bout
    gemm_mma<<<dim3(2, MROWS / 128), 256, G_SMEM>>>(aph, apl, bwh, bwl, bout, kpb, DIMC);

    // SE gate
    se_kernel<<<dim3(DIMC, WN), 256>>>(kpb, se_w1, se_b1, se_w2, se_b2, sbuf);

    // gated weight fp16 hi/lo planes
    prep_w<<<WN * DIMC * 9, 256>>>(kpb, sbuf);

    // grouped conv on tensor cores (fp16 2-pass, 2 taps per barrier)
    conv_mma<<<dim3(2, BATCH, WN), 256, C_SMEM>>>(yb);

    // window reverse + LN + residual
    ln_kernel<<<dim3(IMG, BATCH), 256, 256 * 65 * sizeof(float)>>>(x, yb, ln_g, ln_b, out);
}

// round 17
// speedup vs baseline: 1.1941x; 1.0257x over previous
#include <cuda_runtime.h>
#include <cuda_bf16.h>
#include <cuda_fp16.h>
#include <stdint.h>
#include <math.h>

// ---------------- problem constants ----------------
#define DIMC   256
#define HEADS  8
#define HD     32
#define WSZ    16
#define WN     16
#define KS     3
#define BATCH  16
#define IMG    64
#define TOK    144
#define MROWS  36864               // DIMC*TOK

// ---------------- scratch ----------------
__device__ float          g_qkv[MROWS * 3 * DIMC];
__device__ float          g_kp [MROWS * DIMC];
__device__ float          g_s  [WN * DIMC * DIMC];
__device__ float          g_y  [WN * BATCH * 256 * DIMC];   // conv partial (taps 0-17)
__device__ float          g_y2 [WN * BATCH * 256 * DIMC];   // conv partial (taps 18-35)
__device__ __nv_bfloat16  g_aph[MROWS * DIMC];              // A hi plane (kt, then attn-o)
__device__ __nv_bfloat16  g_apl[MROWS * DIMC];              // A lo plane
__device__ __nv_bfloat16  g_bqh[3 * DIMC * DIMC];           // wqkv^T hi [n][k]
__device__ __nv_bfloat16  g_bql[3 * DIMC * DIMC];
__device__ __nv_bfloat16  g_bwh[DIMC * DIMC];               // wout^T hi [n][k]
__device__ __nv_bfloat16  g_bwl[DIMC * DIMC];
__device__ __half         g_wfh[WN * DIMC * 9 * DIMC];      // gated conv W fp16 hi [w][cout][tap][cin]
__device__ __half         g_wfl[WN * DIMC * 9 * DIMC];      // fp16 lo
__device__ __half         g_xf [BATCH * WN * 4 * 324 * 64]; // x windows fp16 [(b*16+w)*4+chunk][row][cin64]

// ============================================================================
// helpers
// ============================================================================
__device__ __forceinline__ uint32_t smem_u32(const void* p) {
    uint32_t a;
    asm("{ .reg .u64 t; cvta.to.shared.u64 t, %1; cvt.u32.u64 %0, t; }" : "=r"(a) : "l"(p));
    return a;
}
__device__ __forceinline__ void split2(float v, __nv_bfloat16& h, __nv_bfloat16& l) {
    h = __float2bfloat16(v);
    l = __float2bfloat16(v - __bfloat162float(h));
}
__device__ __forceinline__ void mma16816(float* d, const uint32_t* a, const uint32_t* b) {
    asm volatile("mma.sync.aligned.m16n8k16.row.col.f32.bf16.bf16.f32 "
        "{%0,%1,%2,%3}, {%4,%5,%6,%7}, {%8,%9}, {%0,%1,%2,%3};"
        : "+f"(d[0]), "+f"(d[1]), "+f"(d[2]), "+f"(d[3])
        : "r"(a[0]), "r"(a[1]), "r"(a[2]), "r"(a[3]), "r"(b[0]), "r"(b[1]));
}
__device__ __forceinline__ void mma16816h(float* d, const uint32_t* a, const uint32_t* b) {
    asm volatile("mma.sync.aligned.m16n8k16.row.col.f32.f16.f16.f32 "
        "{%0,%1,%2,%3}, {%4,%5,%6,%7}, {%8,%9}, {%0,%1,%2,%3};"
        : "+f"(d[0]), "+f"(d[1]), "+f"(d[2]), "+f"(d[3])
        : "r"(a[0]), "r"(a[1]), "r"(a[2]), "r"(a[3]), "r"(b[0]), "r"(b[1]));
}
__device__ __forceinline__ void ldsm4(uint32_t* r, uint32_t addr) {
    asm volatile("ldmatrix.sync.aligned.m8n8.x4.shared.b16 {%0,%1,%2,%3}, [%4];"
        : "=r"(r[0]), "=r"(r[1]), "=r"(r[2]), "=r"(r[3]) : "r"(addr));
}
__device__ __forceinline__ void cp16(uint32_t dst, const void* src) {
    asm volatile("cp.async.cg.shared.global [%0], [%1], 16;" :: "r"(dst), "l"(src));
}
#define CP_COMMIT() asm volatile("cp.async.commit_group;" ::: "memory")
#define CP_WAIT0()  asm volatile("cp.async.wait_group 0;" ::: "memory")
#define CP_WAIT1()  asm volatile("cp.async.wait_group 1;" ::: "memory")

// packed f32x2 (Blackwell): one instr = two independent fp32 FMAs
typedef unsigned long long u64p;
__device__ __forceinline__ u64p pk2(float lo, float hi) {
    u64p r; asm("mov.b64 %0, {%1, %2};" : "=l"(r) : "f"(lo), "f"(hi)); return r;
}
__device__ __forceinline__ void up2(u64p v, float& lo, float& hi) {
    asm("mov.b64 {%0, %1}, %2;" : "=f"(lo), "=f"(hi) : "l"(v));
}
__device__ __forceinline__ void ffma2(u64p& d, u64p a, u64p b) {
    asm("fma.rn.f32x2 %0, %1, %2, %0;" : "+l"(d) : "l"(a), "l"(b));
}

// Fill a 128x64-elem (16-bit) tile (XOR-swizzled 128B rows) via cp.async.
template <typename T>
__device__ __forceinline__ void fill_tile256(uint32_t dst, const T* src,
                                             int rstride, int tid) {
#pragma unroll
    for (int i = 0; i < 4; i++) {
        int idx = tid + i * 256;
        int r = idx >> 3, q = idx & 7;
        cp16(dst + r * 128 + ((q ^ (r & 7)) << 4), src + (size_t)r * rstride + q * 8);
    }
}

// ============================================================================
// pack kernels
// ============================================================================
__global__ void build_kt_tr(const float* __restrict__ conv_w) {
    __shared__ float sm[64][145];
    const int tid = threadIdx.x;
    const int c1 = blockIdx.x;
    const int cc0 = blockIdx.y * 64;
    const int w = c1 & 15, b = c1 >> 4;
    const float* src = conv_w + ((size_t)(w * 16 + b) * 256 + cc0) * 144;
    for (int idx = tid; idx < 64 * 144; idx += 256) {
        int c = idx / 144, l = idx - c * 144;
        sm[c][l] = src[c * 144 + l];
    }
    __syncthreads();
    for (int idx = tid; idx < 144 * 64; idx += 256) {
        int l = idx >> 6, c = idx & 63;
        __nv_bfloat16 h, lo;
        split2(sm[c][l], h, lo);
        size_t o = (size_t)(c1 * 144 + l) * 256 + cc0 + c;
        g_aph[o] = h;
        g_apl[o] = lo;
    }
}
__global__ void pack_bt(const float* __restrict__ W, __nv_bfloat16* __restrict__ oh,
                        __nv_bfloat16* __restrict__ ol, int N) {
    int idx = blockIdx.x * 256 + threadIdx.x;
    int k = idx & 255;
    int n = idx >> 8;
    __nv_bfloat16 h, l;
    split2(W[(size_t)k * N + n], h, l);
    oh[idx] = h;
    ol[idx] = l;
}
// x windows -> single fp16 plane [(b*16+w)*4+chunk][row=yy*18+xx][cin64]
__global__ void pack_x(const float* __restrict__ x) {
    extern __shared__ float sm[];        // [64][325]
    const int tid = threadIdx.x;
    const int wb = blockIdx.x;           // b*16 + w
    const int b = wb >> 4, w = wb & 15;
    const int h0 = (w >> 2) * WSZ;
    const int w0 = (w & 3) * WSZ;
    for (int chunk = 0; chunk < 4; chunk++) {
        const int c0 = chunk * 64;
        __syncthreads();
        for (int i = tid; i < 64 * 324; i += 256) {
            int ci = i / 324;
            int rem = i - ci * 324;
            int yy = rem / 18;
            int xx = rem - yy * 18;
            float v = 0.f;
            if ((unsigned)(yy - 1) < 16u && (unsigned)(xx - 1) < 16u)
                v = x[((size_t)(b * DIMC + c0 + ci) * IMG + h0 + yy - 1) * IMG + w0 + xx - 1];
            sm[ci * 325 + rem] = v;
        }
        __syncthreads();
        size_t obase = ((size_t)(wb * 4 + chunk)) * 324 * 64;
        for (int i = tid; i < 324 * 64; i += 256) {
            int row = i >> 6, ci = i & 63;
            g_xf[obase + i] = __float2half_rn(sm[ci * 325 + row]);
        }
    }
}

// ============================================================================
// GEMM: C[M,N] = A @ B^T + bias, K=256 (unchanged: bf16 3-pass).
// ============================================================================
#define G_AH 0
#define G_AL 16384
#define G_BH 32768
#define G_BL 49152
#define G_SMEM 65536

__global__ void __launch_bounds__(256, 2)
gemm_mma(const __nv_bfloat16* __restrict__ Ah, const __nv_bfloat16* __restrict__ Al,
         const __nv_bfloat16* __restrict__ Bh, const __nv_bfloat16* __restrict__ Bl,
         const float* __restrict__ bias, float* __restrict__ C, int N) {
    extern __shared__ char smem[];
    const uint32_t sb = smem_u32(smem);
    const int tid = threadIdx.x;
    const int lane = tid & 31;
    const int wid = tid >> 5;
    const int wm = wid & 3, wn = wid >> 2;
    const int m0 = blockIdx.y * 128, n0 = blockIdx.x * 128;
    const int lm = lane & 15, kh = lane >> 4;
    const int quad = lane >> 2, qt = lane & 3;
    const int l7 = lane & 7;
    const int kbit = (lane >> 3) & 1;
    const int nloc = ((lane >> 4) << 3) | l7;

    float acc[2][8][4] = {};

#pragma unroll 1
    for (int kc = 0; kc < 4; kc++) {
        const int k0 = kc * 64;
        fill_tile256(sb + G_AH, Ah + (size_t)m0 * 256 + k0, 256, tid);
        fill_tile256(sb + G_AL, Al + (size_t)m0 * 256 + k0, 256, tid);
        fill_tile256(sb + G_BH, Bh + (size_t)n0 * 256 + k0, 256, tid);
        fill_tile256(sb + G_BL, Bl + (size_t)n0 * 256 + k0, 256, tid);
        CP_COMMIT();
        CP_WAIT0();
        __syncthreads();

        const uint32_t AbH = sb + G_AH;
        const uint32_t AbL = sb + G_AL;
        const uint32_t BbH = sb + G_BH + (wn * 64 + nloc) * 128;
        const uint32_t BbL = sb + G_BL + (wn * 64 + nloc) * 128;
#pragma unroll
        for (int ks = 0; ks < 4; ks++) {
            uint32_t ah[2][4], al[2][4];
#pragma unroll
            for (int fm = 0; fm < 2; fm++) {
                int m = wm * 32 + fm * 16 + lm;
                uint32_t acol = (uint32_t)(((ks * 2 + kh) ^ (lm & 7)) << 4);
                ldsm4(ah[fm], AbH + m * 128 + acol);
                ldsm4(al[fm], AbL + m * 128 + acol);
            }
            const uint32_t bcol = (uint32_t)(((ks * 2 + kbit) ^ l7) << 4);
            uint32_t bh[4][4], bl[4][4];
#pragma unroll
            for (int p = 0; p < 4; p++) {
                ldsm4(bh[p], BbH + p * 2048 + bcol);
                ldsm4(bl[p], BbL + p * 2048 + bcol);
            }
#pragma unroll
            for (int p = 0; p < 4; p++)
#pragma unroll
                for (int fm = 0; fm < 2; fm++) {
                    mma16816(acc[fm][2 * p],     ah[fm], bh[p]);
                    mma16816(acc[fm][2 * p + 1], ah[fm], bh[p] + 2);
                }
#pragma unroll
            for (int p = 0; p < 4; p++)
#pragma unroll
                for (int fm = 0; fm < 2; fm++) {
                    mma16816(acc[fm][2 * p],     ah[fm], bl[p]);
                    mma16816(acc[fm][2 * p + 1], ah[fm], bl[p] + 2);
                }
#pragma unroll
            for (int p = 0; p < 4; p++)
#pragma unroll
                for (int fm = 0; fm < 2; fm++) {
                    mma16816(acc[fm][2 * p],     al[fm], bh[p]);
                    mma16816(acc[fm][2 * p + 1], al[fm], bh[p] + 2);
                }
        }
        __syncthreads();
    }

#pragma unroll
    for (int fm = 0; fm < 2; fm++) {
        int m = m0 + wm * 32 + fm * 16 + quad;
#pragma unroll
        for (int fn = 0; fn < 8; fn++) {
            int col = n0 + wn * 64 + fn * 8 + qt * 2;
            float b0 = bias[col], b1 = bias[col + 1];
            float* c = acc[fm][fn];
            *(float2*)&C[(size_t)m * N + col]       = make_float2(c[0] + b0, c[1] + b1);
            *(float2*)&C[(size_t)(m + 8) * N + col] = make_float2(c[2] + b0, c[3] + b1);
        }
    }
}

// ============================================================================
// attention — single pass, packed f32x2 FMA (unchanged)
// ============================================================================
__global__ void attn_kernel(const float* __restrict__ qkv) {
    const int c1 = blockIdx.x;
    const int h  = blockIdx.y;
    __shared__ float ks[TOK][HD];
    __shared__ float vs[TOK][HD];

    for (int idx = threadIdx.x; idx < TOK * HD; idx += blockDim.x) {
        int t = idx >> 5, e = idx & 31;
        size_t base = (size_t)(c1 * TOK + t) * 768 + h * HD + e;
        ks[t][e] = qkv[base + 256];
        vs[t][e] = qkv[base + 512];
    }
    __syncthreads();

    const int t = threadIdx.x;
    if (t < TOK) {
        const float scale = 0.17677669529663687f;
        u64p q2[16];
        {
            const float2* qsrc = (const float2*)(qkv + (size_t)(c1 * TOK + t) * 768 + h * HD);
#pragma unroll
            for (int i = 0; i < 16; i++) {
                float2 v = qsrc[i];
                q2[i] = pk2(v.x * scale, v.y * scale);
            }
        }

        u64p a2[16];
#pragma unroll
        for (int i = 0; i < 16; i++) a2[i] = pk2(0.f, 0.f);
        float denom = 0.f;

        for (int j = 0; j < TOK; j++) {
            const u64p* k2 = (const u64p*)ks[j];
            u64p s0 = pk2(0.f, 0.f), s1 = s0, s2 = s0, s3 = s0;
#pragma unroll
            for (int i = 0; i < 16; i += 4) {
                ffma2(s0, q2[i],     k2[i]);
                ffma2(s1, q2[i + 1], k2[i + 1]);
                ffma2(s2, q2[i + 2], k2[i + 2]);
                ffma2(s3, q2[i + 3], k2[i + 3]);
            }
            float x0, x1, y0, y1, z0, z1, w0, w1;
            up2(s0, x0, x1); up2(s1, y0, y1); up2(s2, z0, z1); up2(s3, w0, w1);
            float sc = ((x0 + x1) + (y0 + y1)) + ((z0 + z1) + (w0 + w1));
            float pexp = __expf(sc);
            denom += pexp;
            u64p pe2 = pk2(pexp, pexp);
            const u64p* v2 = (const u64p*)vs[j];
#pragma unroll
            for (int i = 0; i < 16; i++) ffma2(a2[i], pe2, v2[i]);
        }
        float inv = 1.f / denom;
        size_t ob = (size_t)(c1 * TOK + t) * DIMC + h * HD;
#pragma unroll
        for (int i = 0; i < 16; i++) {
            float v0, v1;
            up2(a2[i], v0, v1);
            __nv_bfloat16 h0, l0, h1, l1;
            split2(v0 * inv, h0, l0);
            split2(v1 * inv, h1, l1);
            g_aph[ob + i * 2]     = h0;
            g_aph[ob + i * 2 + 1] = h1;
            g_apl[ob + i * 2]     = l0;
            g_apl[ob + i * 2 + 1] = l1;
        }
    }
}

// ============================================================================
// SE gate (unchanged)
// ============================================================================
__global__ void se_kernel(const float* __restrict__ kp,
                          const float* __restrict__ se_w1, const float* __restrict__ se_b1,
                          const float* __restrict__ se_w2, const float* __restrict__ se_b2,
                          float* __restrict__ s_out) {
    const int i = blockIdx.x;
    const int w = blockIdx.y;
    __shared__ float pooled[DIMC];
    __shared__ float hsm[16];
    const int j = threadIdx.x;

    size_t base = (size_t)(i * TOK + w * 9) * DIMC + j;
    float p = 0.f;
#pragma unroll
    for (int tap = 0; tap < 9; tap++) p += kp[base + (size_t)tap * DIMC];
    pooled[j] = p * (1.f / 9.f);
    __syncthreads();

    if (j < 16) {
        float hv = se_b1[w * 16 + j];
        const float* w1 = se_w1 + (size_t)(w * 16 + j) * DIMC;
        for (int c = 0; c < DIMC; c++) hv += pooled[c] * w1[c];
        hsm[j] = fmaxf(hv, 0.f);
    }
    __syncthreads();

    float acc = se_b2[w * DIMC + j];
    const float* w2 = se_w2 + (size_t)(w * DIMC + j) * 16;
#pragma unroll
    for (int k = 0; k < 16; k++) acc += hsm[k] * w2[k];
    s_out[(size_t)(w * DIMC + i) * DIMC + j] = 1.f / (1.f + __expf(-acc));
}

// ============================================================================
// weight prep -> fp16 hi/lo planes  [((w*256+cout)*9+tap)*256 + cin]
// ============================================================================
__global__ void prep_w(const float* __restrict__ kp, const float* __restrict__ s) {
    int idx = blockIdx.x * 256 + threadIdx.x;
    int cin = idx & 255;
    int t2  = idx >> 8;
    int tap = t2 % 9;
    int t3  = t2 / 9;
    int cout = t3 & 255;
    int w    = t3 >> 8;
    float v = kp[(size_t)(cout * TOK + w * 9 + tap) * DIMC + cin]
            * s[(size_t)(w * DIMC + cout) * DIMC + cin];
    __half h = __float2half_rn(v);
    __half l = __float2half_rn(v - __half2float(h));
    g_wfh[idx] = h;
    g_wfl[idx] = l;
}

// ============================================================================
// grouped conv: warp-MMA fp16 implicit GEMM, 2-pass (A fp16, W hi/lo fp16).
// K-SPLIT: grid (4,b,w); khalf = bx>>1 owns taps [khalf*18, +18) (2 cin-chunks),
// nhalf = bx&1 owns couts [nhalf*128, +128). Partials -> g_y / g_y2.
// 2 taps per barrier round (9 rounds); B = 2 sets x 2 tiles; xs double-buffered.
// smem: XS0 41472 | XS1 41472 | B 4 x 32768 = 214016 B.
// ============================================================================
#define C_XSBUF 41472
#define C_BBASE 82944
#define C_SMEM  214016

__global__ void __launch_bounds__(256, 1)
conv_mma(float* __restrict__ y1, float* __restrict__ y2) {
    extern __shared__ char smem[];
    const uint32_t sb = smem_u32(smem);
    const int tid = threadIdx.x;
    const int lane = tid & 31;
    const int wid = tid >> 5;
    const int wm = wid & 3, wn = wid >> 2;
    const int khalf = blockIdx.x >> 1;
    const int nhalf = blockIdx.x & 1;
    const int b = blockIdx.y;
    const int w = blockIdx.z;
    const int lm = lane & 15, kh = lane >> 4;
    const int quad = lane >> 2, qt = lane & 3;
    const int l7 = lane & 7;
    const int kbit = (lane >> 3) & 1;
    const int nloc = ((lane >> 4) << 3) | l7;
    const int wb = b * 16 + w;
    const int ktbase = khalf * 18;
    const int c0 = khalf * 2;           // first chunk for this CTA

    const __half* wfh = g_wfh + ((size_t)(w * 256 + nhalf * 128) * 9) * 256;
    const __half* wfl = g_wfl + ((size_t)(w * 256 + nhalf * 128) * 9) * 256;

    float acc[4][8][4] = {};

    auto xsfill = [&](int chunk) {
        const __half* src = g_xf + ((size_t)(wb * 4 + chunk)) * 324 * 64;
        const uint32_t xbuf = sb + (chunk & 1) * C_XSBUF;
        for (int i = tid; i < 2592; i += 256) {
            int r = i >> 3, q = i & 7;
            cp16(xbuf + r * 128 + ((q ^ (r & 7)) << 4), src + r * 64 + q * 8);
        }
    };
    // fill set t%2 with taps ktbase+2t, +1 (hi+lo planes each)
    auto bfill2 = [&](int t) {
#pragma unroll
        for (int j = 0; j < 2; j++) {
            int kt = ktbase + 2 * t + j;
            int nc = kt / 9, nt = kt - nc * 9;
            uint32_t d = sb + C_BBASE + (t & 1) * 65536 + j * 32768;
            fill_tile256(d,         wfh + (size_t)nt * 256 + nc * 64, 2304, tid);
            fill_tile256(d + 16384, wfl + (size_t)nt * 256 + nc * 64, 2304, tid);
        }
    };

    // prologue: xs(c0), B set 0 (taps ktbase, ktbase+1)
    xsfill(c0);  CP_COMMIT();
    bfill2(0);   CP_COMMIT();

#pragma unroll 1
    for (int t = 0; t < 9; t++) {
        CP_WAIT0();          // set t and any earlier xs commit are ready
        __syncthreads();     // all warps done reading set (t+1)%2 from round t-1

        if (t == 2) { xsfill(c0 + 1); CP_COMMIT(); }   // needed from kt=ktbase+9 (round 4)
        if (t < 8)  { bfill2(t + 1); CP_COMMIT(); }

#pragma unroll
        for (int j = 0; j < 2; j++) {
            const int kt = ktbase + 2 * t + j;
            const int chunk = kt / 9;
            const uint32_t Xb  = sb + (chunk & 1) * C_XSBUF;
            const uint32_t BbH = sb + C_BBASE + (t & 1) * 65536 + j * 32768
                               + (wn * 64 + nloc) * 128;
            const uint32_t BbL = BbH + 16384;
            const int tap = kt - chunk * 9;
            const int ky = tap / 3, kx = tap - ky * 3;
            int arow[4];
#pragma unroll
            for (int fm = 0; fm < 4; fm++) {
                int p = wm * 64 + fm * 16 + lm;
                arow[fm] = ((p >> 4) + ky) * 18 + (p & 15) + kx;
            }

#pragma unroll
            for (int ksl = 0; ksl < 4; ksl++) {
                uint32_t a[4][4];
#pragma unroll
                for (int fm = 0; fm < 4; fm++) {
                    uint32_t acol = (uint32_t)(((ksl * 2 + kh) ^ (arow[fm] & 7)) << 4);
                    ldsm4(a[fm], Xb + arow[fm] * 128 + acol);
                }
                const uint32_t bcol = (uint32_t)(((ksl * 2 + kbit) ^ l7) << 4);
                uint32_t bh[4][4], bl[4][4];
#pragma unroll
                for (int p = 0; p < 4; p++) {
                    ldsm4(bh[p], BbH + p * 2048 + bcol);
                    ldsm4(bl[p], BbL + p * 2048 + bcol);
                }
                // sweep 1: A * Wh  (32 independent accumulators)
#pragma unroll
                for (int p = 0; p < 4; p++)
#pragma unroll
                    for (int fm = 0; fm < 4; fm++) {
                        mma16816h(acc[fm][2 * p],     a[fm], bh[p]);
                        mma16816h(acc[fm][2 * p + 1], a[fm], bh[p] + 2);
                    }
                // sweep 2: A * Wl
#pragma unroll
                for (int p = 0; p < 4; p++)
#pragma unroll
                    for (int fm = 0; fm < 4; fm++) {
                        mma16816h(acc[fm][2 * p],     a[fm], bl[p]);
                        mma16816h(acc[fm][2 * p + 1], a[fm], bl[p] + 2);
                    }
            }
        }
    }

    // ---- epilogue: partial to its K-half plane ----
    float* ybase = (khalf ? y2 : y1)
                 + (size_t)((w * 16 + b) * 256) * 256 + nhalf * 128;
#pragma unroll
    for (int fm = 0; fm < 4; fm++) {
        int pos = wm * 64 + fm * 16 + quad;
#pragma unroll
        for (int fn = 0; fn < 8; fn++) {
            int col = wn * 64 + fn * 8 + qt * 2;
            float* c = acc[fm][fn];
            *(float2*)(ybase + (size_t)pos * 256 + col)       = make_float2(c[0], c[1]);
            *(float2*)(ybase + (size_t)(pos + 8) * 256 + col) = make_float2(c[2], c[3]);
        }
    }
}

// ============================================================================
// window reverse + channel LayerNorm + residual; sums the two conv partials.
// ============================================================================
__global__ void ln_kernel(const float* __restrict__ x,
                          const float* __restrict__ y1, const float* __restrict__ y2,
                          const float* __restrict__ ln_g, const float* __restrict__ ln_b,
                          float* __restrict__ out) {
    extern __shared__ float sm[];
    __shared__ float red[2][4][64];
    __shared__ float mu[64], rs[64];

    const int yy = blockIdx.x;
    const int b  = blockIdx.y;
    const int t  = threadIdx.x;
    const int hi = yy >> 4;
    const int py = yy & 15;

    for (int xx = 0; xx < 64; xx++) {
        int w = hi * 4 + (xx >> 4);
        int p = py * 16 + (xx & 15);
        size_t idx = ((size_t)((w * 16 + b) * 256 + p)) * DIMC + t;
        sm[t * 65 + xx] = y1[idx] + y2[idx];
    }
    __syncthreads();

    {
        int xx = t & 63, part = t >> 6;
        float s1 = 0.f, s2 = 0.f;
        for (int c = part * 64; c < part * 64 + 64; c++) {
            float v = sm[c * 65 + xx];
            s1 += v; s2 += v * v;
        }
        red[0][part][xx] = s1;
        red[1][part][xx] = s2;
    }
    __syncthreads();
    if (t < 64) {
        float S = 0.f, S2 = 0.f;
#pragma unroll
        for (int p2 = 0; p2 < 4; p2++) { S += red[0][p2][t]; S2 += red[1][p2][t]; }
        float m = S * (1.f / 256.f);
        float var = S2 * (1.f / 256.f) - m * m;
        mu[t] = m;
        rs[t] = rsqrtf(var + 1e-5f);
    }
    __syncthreads();

    for (int idx = t; idx < 256 * 64; idx += 256) {
        int c  = idx >> 6;
        int xi = idx & 63;
        float v = (sm[c * 65 + xi] - mu[xi]) * rs[xi] * ln_g[c] + ln_b[c];
        size_t oidx = ((size_t)(b * DIMC + c) * IMG + yy) * IMG + xi;
        out[oidx] = x[oidx] + v;
    }
}

// ============================================================================
// launch
// ============================================================================
extern "C" void kernel_launch(void* const* d_in, const int* in_sizes, int n_in,
                              void* d_out, int out_size) {
    const float* x      = (const float*)d_in[0];
    const float* conv_w = (const float*)d_in[1];
    const float* wqkv   = (const float*)d_in[2];
    const float* bqkv   = (const float*)d_in[3];
    const float* wout   = (const float*)d_in[4];
    const float* bout   = (const float*)d_in[5];
    const float* se_w1  = (const float*)d_in[6];
    const float* se_b1  = (const float*)d_in[7];
    const float* se_w2  = (const float*)d_in[8];
    const float* se_b2  = (const float*)d_in[9];
    const float* ln_g   = (const float*)d_in[10];
    const float* ln_b   = (const float*)d_in[11];
    float* out = (float*)d_out;

    float *qkvb, *kpb, *sbuf, *yb, *yb2;
    __nv_bfloat16 *aph, *apl, *bqh, *bql, *bwh, *bwl;
    cudaGetSymbolAddress((void**)&qkvb, g_qkv);
    cudaGetSymbolAddress((void**)&kpb,  g_kp);
    cudaGetSymbolAddress((void**)&sbuf, g_s);
    cudaGetSymbolAddress((void**)&yb,   g_y);
    cudaGetSymbolAddress((void**)&yb2,  g_y2);
    cudaGetSymbolAddress((void**)&aph,  g_aph);
    cudaGetSymbolAddress((void**)&apl,  g_apl);
    cudaGetSymbolAddress((void**)&bqh,  g_bqh);
    cudaGetSymbolAddress((void**)&bql,  g_bql);
    cudaGetSymbolAddress((void**)&bwh,  g_bwh);
    cudaGetSymbolAddress((void**)&bwl,  g_bwl);

    cudaFuncSetAttribute(conv_mma, cudaFuncAttributeMaxDynamicSharedMemorySize, C_SMEM);
    cudaFuncSetAttribute(gemm_mma, cudaFuncAttributeMaxDynamicSharedMemorySize, G_SMEM);
    cudaFuncSetAttribute(pack_x, cudaFuncAttributeMaxDynamicSharedMemorySize,
                         64 * 325 * (int)sizeof(float));
    cudaFuncSetAttribute(ln_kernel, cudaFuncAttributeMaxDynamicSharedMemorySize,
                         256 * 65 * (int)sizeof(float));

    // pack weights
    pack_bt<<<3 * DIMC, 256>>>(wqkv, bqh, bql, 3 * DIMC);
    pack_bt<<<DIMC, 256>>>(wout, bwh, bwl, DIMC);

    // kt planes from conv_w (tiled transpose)
    build_kt_tr<<<dim3(256, 4), 256>>>(conv_w);

    // qkv = kt @ wqkv + bqkv
    gemm_mma<<<dim3(6, MROWS / 128), 256, G_SMEM>>>(aph, apl, bqh, bql, bqkv, qkvb, 3 * DIMC);

    // x windows pack (independent; only needed before conv)
    pack_x<<<BATCH * WN, 256, 64 * 325 * sizeof(float)>>>(x);

    // attention (writes A planes for wout gemm)
    attn_kernel<<<dim3(DIMC, HEADS), 160>>>(qkvb);

    // kp = o @ wout + bout
    gemm_mma<<<dim3(2, MROWS / 128), 256, G_SMEM>>>(aph, apl, bwh, bwl, bout, kpb, DIMC);

    // SE gate
    se_kernel<<<dim3(DIMC, WN), 256>>>(kpb, se_w1, se_b1, se_w2, se_b2, sbuf);

    // gated weight fp16 hi/lo planes
    prep_w<<<WN * DIMC * 9, 256>>>(kpb, sbuf);

    // grouped conv on tensor cores (fp16 2-pass, K-split across 2 CTAs)
    conv_mma<<<dim3(4, BATCH, WN), 256, C_SMEM>>>(yb, yb2);

    // window reverse + LN + residual (sums partials)
    ln_kernel<<<dim3(IMG, BATCH), 256, 256 * 65 * sizeof(float)>>>(x, yb, yb2, ln_g, ln_b, out);
}